// round 12
// baseline (speedup 1.0000x reference)
#include <cuda_runtime.h>
#include <cuda_bf16.h>
#include <cstdint>

#define NN   16384
#define HID  256
#define NEMAX 1048576
#define ETOT (NEMAX + NN)

// ---------------- device scratch ----------------
__device__ float g_h1[(size_t)NN * HID];
__device__ float g_h2[(size_t)NN * HID];
__device__ int   g_deg[NN];
__device__ float g_dinv[NN];
__device__ int   g_rowstart[NN + 1];
__device__ int   g_cursor[NN];
__device__ int   g_csr[ETOT];
__device__ float g_sa[NN];
__device__ float g_sb[NN];
// bf16 transposed weights [N=256, K] row-major
__device__ __nv_bfloat16 g_B1[(size_t)HID * NN];
__device__ __nv_bfloat16 g_B2[(size_t)HID * HID];

__device__ __forceinline__ uint32_t smem_u32(const void* p) {
    uint32_t a;
    asm("{ .reg .u64 t; cvta.to.shared.u64 t, %1; cvt.u32.u64 %0, t; }" : "=r"(a) : "l"(p));
    return a;
}
__device__ __forceinline__ void ldm_x4(uint32_t addr, uint32_t* r) {
    asm volatile("ldmatrix.sync.aligned.m8n8.x4.shared.b16 {%0,%1,%2,%3}, [%4];"
                 : "=r"(r[0]), "=r"(r[1]), "=r"(r[2]), "=r"(r[3]) : "r"(addr));
}
__device__ __forceinline__ void mma_bf16(float* c, const uint32_t* a, const uint32_t* b) {
    asm volatile("mma.sync.aligned.m16n8k16.row.col.f32.bf16.bf16.f32 "
                 "{%0,%1,%2,%3}, {%4,%5,%6,%7}, {%8,%9}, {%0,%1,%2,%3};"
                 : "+f"(c[0]), "+f"(c[1]), "+f"(c[2]), "+f"(c[3])
                 : "r"(a[0]), "r"(a[1]), "r"(a[2]), "r"(a[3]), "r"(b[0]), "r"(b[1]));
}
__device__ __forceinline__ void cp16(uint32_t dst, const void* src) {
    asm volatile("cp.async.cg.shared.global [%0], [%1], 16;" :: "r"(dst), "l"(src));
}
#define CP_COMMIT() asm volatile("cp.async.commit_group;" ::: "memory")
#define CP_WAIT0()  asm volatile("cp.async.wait_group 0;" ::: "memory")

// ---------------- weight prep: W[K,256] fp32 -> gB[256,K] bf16 transposed ----
__global__ void k_prep_B(const float* __restrict__ W, __nv_bfloat16* __restrict__ gB, int K) {
    __shared__ float tile[32][33];
    int t = threadIdx.x;
    int k0 = blockIdx.x * 32, n0 = blockIdx.y * 32;
#pragma unroll
    for (int p = 0; p < 4; p++) {
        int idx = t + 256 * p, i = idx >> 5, j = idx & 31;
        tile[i][j] = W[(size_t)(k0 + i) * HID + n0 + j];
    }
    __syncthreads();
    int jp = t >> 3, i0 = (t & 7) * 4;
    __nv_bfloat16 o[4];
#pragma unroll
    for (int q = 0; q < 4; q++) o[q] = __float2bfloat16(tile[i0 + q][jp]);
    *(uint2*)&gB[(size_t)(n0 + jp) * K + k0 + i0] = *(uint2*)o;
}

// ---------------- single-pass bf16 GEMM: C[M,256] = A[M,K] @ W ----
// CTA 128x256 (full N), 8 warps (2M x 4N), warp tile 64x64, BK=64, 2-stage, 1 CTA/SM.
// Row stride 144B (16x9 -> conflict-free ldmatrix). Stage: A 128x144 | B 256x144 = 55296B.
#define ROWB    144
#define A_BYTES 18432
#define STAGE_BYTES 55296
#define HG_SMEM (2 * STAGE_BYTES)

__global__ __launch_bounds__(256, 1)
void k_hgemm(const float* __restrict__ A, const __nv_bfloat16* __restrict__ gB,
             float* __restrict__ C, int K) {
    extern __shared__ char smem[];
    const uint32_t sb = smem_u32(smem);
    const int t = threadIdx.x;
    const int lane = t & 31, w = t >> 5;
    const int wm = w & 1, wn = w >> 1;              // 2M x 4N warps, warp tile 64x64
    const int mo = blockIdx.x * 128;
    const int nc = K / 64;

    const int arow = t >> 1, ahalf = t & 1;         // A: 128 rows x 64 fp32, 2 thr/row
    const int brow = t;                              // B: 256 rows x 64 bf16, 1 thr/row

    float4 xa[8];

    auto ldgA = [&](int c) {
        const float* Ap = A + (size_t)(mo + arow) * K + c * 64 + ahalf * 32;
#pragma unroll
        for (int q = 0; q < 8; q++) xa[q] = *(const float4*)(Ap + 4 * q);
    };
    auto cpB = [&](int c, int st) {
        uint32_t dst = sb + st * STAGE_BYTES + A_BYTES + brow * ROWB;
        const __nv_bfloat16* Bp = gB + (size_t)brow * K + c * 64;
#pragma unroll
        for (int q = 0; q < 8; q++) cp16(dst + 16 * q, Bp + 8 * q);
    };
    auto stsA = [&](int st) {
        char* base = smem + st * STAGE_BYTES;
        __nv_bfloat16 h[32];
#pragma unroll
        for (int q = 0; q < 8; q++) {
            h[q * 4 + 0] = __float2bfloat16(xa[q].x);
            h[q * 4 + 1] = __float2bfloat16(xa[q].y);
            h[q * 4 + 2] = __float2bfloat16(xa[q].z);
            h[q * 4 + 3] = __float2bfloat16(xa[q].w);
        }
        uint32_t aoff = (uint32_t)arow * ROWB + (uint32_t)ahalf * 64;
#pragma unroll
        for (int q = 0; q < 4; q++)
            *(uint4*)(base + aoff + 16 * q) = *(uint4*)&h[8 * q];
    };

    float acc[4][8][4];
#pragma unroll
    for (int i = 0; i < 4; i++)
#pragma unroll
        for (int j = 0; j < 8; j++)
#pragma unroll
            for (int e = 0; e < 4; e++) acc[i][j][e] = 0.f;

    const int lm = lane & 7, sel = lane >> 3;
    const uint32_t a_row_off = (uint32_t)(wm * 64 + (sel & 1) * 8 + lm) * ROWB + (uint32_t)(sel >> 1) * 16;
    const uint32_t b_row_off = (uint32_t)(wn * 64 + (sel >> 1) * 8 + lm) * ROWB + (uint32_t)(sel & 1) * 16;

    // fragment double buffer across kk
    uint32_t af[2][4][4];
    uint32_t bf[2][8][2];
    auto ldfrag = [&](uint32_t stage, int kk, int pb) {
        const uint32_t kb = (uint32_t)kk * 32;
#pragma unroll
        for (int mt = 0; mt < 4; mt++)
            ldm_x4(stage + a_row_off + (uint32_t)mt * (16 * ROWB) + kb, af[pb][mt]);
#pragma unroll
        for (int pr = 0; pr < 4; pr++) {
            uint32_t r[4];
            ldm_x4(stage + A_BYTES + b_row_off + (uint32_t)pr * (16 * ROWB) + kb, r);
            bf[pb][2 * pr][0] = r[0]; bf[pb][2 * pr][1] = r[1];
            bf[pb][2 * pr + 1][0] = r[2]; bf[pb][2 * pr + 1][1] = r[3];
        }
    };
    auto do_mma = [&](int pb) {
#pragma unroll
        for (int mt = 0; mt < 4; mt++)
#pragma unroll
            for (int nt = 0; nt < 8; nt++) mma_bf16(acc[mt][nt], af[pb][mt], bf[pb][nt]);
    };

    // prologue
    cpB(0, 0);
    CP_COMMIT();
    ldgA(0);
    stsA(0);
    CP_WAIT0();
    __syncthreads();

    for (int c = 0; c < nc; c++) {
        const int st = c & 1;
        if (c + 1 < nc) {
            cpB(c + 1, st ^ 1);
            CP_COMMIT();
            ldgA(c + 1);
        }

        const uint32_t stage = sb + st * STAGE_BYTES;
        ldfrag(stage, 0, 0);
#pragma unroll
        for (int kk = 0; kk < 4; kk++) {
            if (kk < 3) ldfrag(stage, kk + 1, (kk + 1) & 1);
            do_mma(kk & 1);
        }

        if (c + 1 < nc) stsA(st ^ 1);
        CP_WAIT0();
        __syncthreads();
    }

    // epilogue
#pragma unroll
    for (int mt = 0; mt < 4; mt++) {
        int r0 = mo + wm * 64 + mt * 16 + (lane >> 2);
#pragma unroll
        for (int nt = 0; nt < 8; nt++) {
            int cb = wn * 64 + nt * 8 + (lane & 3) * 2;
            float2 v0 = make_float2(acc[mt][nt][0], acc[mt][nt][1]);
            float2 v1 = make_float2(acc[mt][nt][2], acc[mt][nt][3]);
            *(float2*)(C + (size_t)r0 * HID + cb)       = v0;
            *(float2*)(C + (size_t)(r0 + 8) * HID + cb) = v1;
        }
    }
}

// ---------------- degree / CSR construction ----------------
__global__ void k_init_deg() {
    int i = blockIdx.x * blockDim.x + threadIdx.x;
    if (i < NN) g_deg[i] = 1;
}
__global__ void k_count_deg(const int* __restrict__ dst, int E) {
    int i = blockIdx.x * blockDim.x + threadIdx.x;
    if (i < E) atomicAdd(&g_deg[dst[i]], 1);
}
__global__ void k_dinv() {
    int i = blockIdx.x * blockDim.x + threadIdx.x;
    if (i < NN) g_dinv[i] = rsqrtf((float)g_deg[i]);
}
__global__ void k_scan() {
    __shared__ int sh[1024];
    int tid = threadIdx.x;
    int local[16];
    int sum = 0;
#pragma unroll
    for (int i = 0; i < 16; i++) { local[i] = g_deg[tid * 16 + i]; sum += local[i]; }
    sh[tid] = sum;
    __syncthreads();
    for (int off = 1; off < 1024; off <<= 1) {
        int v = (tid >= off) ? sh[tid - off] : 0;
        __syncthreads();
        sh[tid] += v;
        __syncthreads();
    }
    int run = (tid == 0) ? 0 : sh[tid - 1];
#pragma unroll
    for (int i = 0; i < 16; i++) {
        g_rowstart[tid * 16 + i] = run;
        g_cursor[tid * 16 + i]   = run;
        run += local[i];
    }
    if (tid == 1023) g_rowstart[NN] = run;
}
__global__ void k_fill(const int* __restrict__ src, const int* __restrict__ dst, int E) {
    int i = blockIdx.x * blockDim.x + threadIdx.x;
    if (i >= E + NN) return;
    int s, d;
    if (i < E) { s = src[i]; d = dst[i]; }
    else       { s = i - E; d = s; }
    int slot = atomicAdd(&g_cursor[d], 1);
    g_csr[slot] = s;
}
__global__ void k_sort_rows() {
    __shared__ int s[1024];
    int r = blockIdx.x;
    int beg = g_rowstart[r], end = g_rowstart[r + 1];
    int len = end - beg;
    if (len <= 1 || len > 1024) return;
    for (int i = threadIdx.x; i < len; i += blockDim.x) s[i] = g_csr[beg + i];
    __syncthreads();
    for (int ph = 0; ph < len; ph++) {
        int off = ph & 1;
        for (int j = off + 2 * (int)threadIdx.x; j + 1 < len; j += 2 * (int)blockDim.x) {
            int a = s[j], b = s[j + 1];
            if (a > b) { s[j] = b; s[j + 1] = a; }
        }
        __syncthreads();
    }
    for (int i = threadIdx.x; i < len; i += blockDim.x) g_csr[beg + i] = s[i];
}

// ---------------- aggregation (optionally fused edge-score projection) ----------------
__global__ void k_agg(const float* __restrict__ hin, float* __restrict__ hout,
                      const float* __restrict__ bias, const float* __restrict__ linW) {
    int v = blockIdx.x;
    int t = threadIdx.x;
    int beg = g_rowstart[v], end = g_rowstart[v + 1];
    float dv = g_dinv[v];
    __shared__ int   ssrc[256];
    __shared__ float snorm[256];
    __shared__ float red[256];
    float acc = 0.f;
    for (int base = beg; base < end; base += 256) {
        int n = min(256, end - base);
        if (t < n) {
            int s = g_csr[base + t];
            ssrc[t]  = s * HID;
            snorm[t] = g_dinv[s] * dv;
        }
        __syncthreads();
        int j = 0;
        for (; j + 4 <= n; j += 4) {
            float x0 = hin[ssrc[j]     + t];
            float x1 = hin[ssrc[j + 1] + t];
            float x2 = hin[ssrc[j + 2] + t];
            float x3 = hin[ssrc[j + 3] + t];
            acc += x0 * snorm[j] + x1 * snorm[j + 1] + x2 * snorm[j + 2] + x3 * snorm[j + 3];
        }
        for (; j < n; j++) acc += hin[ssrc[j] + t] * snorm[j];
        __syncthreads();
    }
    float r = acc + bias[t];
    r = r > 0.f ? r : 0.f;
    hout[(size_t)v * HID + t] = r;

    if (linW) {   // layer-2: also produce per-node edge-score partials
        red[t] = r * linW[t];
        __syncthreads();
        for (int s = 128; s > 0; s >>= 1) {
            if (t < s) red[t] += red[t + s];
            __syncthreads();
        }
        if (t == 0) g_sa[v] = red[0];
        __syncthreads();
        red[t] = r * linW[HID + t];
        __syncthreads();
        for (int s = 128; s > 0; s >>= 1) {
            if (t < s) red[t] += red[t + s];
            __syncthreads();
        }
        if (t == 0) g_sb[v] = red[0];
    }
}

// ---------------- edge scoring ----------------
__global__ void k_edge_out(const int* __restrict__ src, const int* __restrict__ dst,
                           const float* __restrict__ linb, float* __restrict__ out, int E) {
    int i = blockIdx.x * blockDim.x + threadIdx.x;
    if (i < E) out[i] = g_sa[src[i]] + g_sb[dst[i]] + linb[0];
}

// ---------------- launch ----------------
extern "C" void kernel_launch(void* const* d_in, const int* in_sizes, int n_in,
                              void* d_out, int out_size) {
    const float* x    = (const float*)d_in[0];
    const int*   ei   = (const int*)d_in[1];
    const float* W1   = (const float*)d_in[2];
    const float* b1   = (const float*)d_in[3];
    const float* W2   = (const float*)d_in[4];
    const float* b2   = (const float*)d_in[5];
    const float* linW = (const float*)d_in[6];
    const float* linb = (const float*)d_in[7];
    float* out = (float*)d_out;

    int E = in_sizes[1] / 2;
    const int* esrc = ei;
    const int* edst = ei + E;

    float *h1, *h2;
    __nv_bfloat16 *B1, *B2;
    cudaGetSymbolAddress((void**)&h1, g_h1);
    cudaGetSymbolAddress((void**)&h2, g_h2);
    cudaGetSymbolAddress((void**)&B1, g_B1);
    cudaGetSymbolAddress((void**)&B2, g_B2);

    cudaFuncSetAttribute(k_hgemm, cudaFuncAttributeMaxDynamicSharedMemorySize, HG_SMEM);

    // launch order arranged so k_hgemm (layer 1) is launch index 3 -> ncu captures it
    k_prep_B<<<dim3(NN / 32, HID / 32), 256>>>(W1, B1, NN);        // 0
    k_prep_B<<<dim3(HID / 32, HID / 32), 256>>>(W2, B2, HID);      // 1
    k_init_deg<<<NN / 256, 256>>>();                               // 2
    k_hgemm<<<NN / 128, 256, HG_SMEM>>>(x, B1, h1, NN);            // 3 <- profile target

    // graph structure
    k_count_deg<<<(E + 255) / 256, 256>>>(edst, E);
    k_dinv<<<NN / 256, 256>>>();
    k_scan<<<1, 1024>>>();
    k_fill<<<(E + NN + 255) / 256, 256>>>(esrc, edst, E);
    k_sort_rows<<<NN, 256>>>();

    // layer 1 aggregation
    k_agg<<<NN, 256>>>(h1, h2, b1, (const float*)nullptr);
    // layer 2 (agg fused with edge-score projection)
    k_hgemm<<<NN / 128, 256, HG_SMEM>>>(h2, B2, h1, HID);
    k_agg<<<NN, 256>>>(h1, h2, b2, linW);

    // edge scores
    k_edge_out<<<(E + 255) / 256, 256>>>(esrc, edst, linb, out, E);
}

// round 13
// speedup vs baseline: 1.0368x; 1.0368x over previous
#include <cuda_runtime.h>
#include <cuda_bf16.h>
#include <cstdint>

#define NN   16384
#define HID  256
#define NEMAX 1048576
#define ETOT (NEMAX + NN)

// ---------------- device scratch ----------------
__device__ __nv_bfloat16 g_hb1[(size_t)NN * HID];  // GEMM outputs (bf16)
__device__ __nv_bfloat16 g_hb2[(size_t)NN * HID];  // agg1 output (bf16) = GEMM2 A
__device__ int   g_deg[NN];
__device__ float g_dinv[NN];
__device__ int   g_rowstart[NN + 1];
__device__ int   g_cursor[NN];
__device__ int   g_csr[ETOT];
__device__ float g_sa[NN];
__device__ float g_sb[NN];
// bf16 transposed weights [N=256, K] row-major
__device__ __nv_bfloat16 g_B1[(size_t)HID * NN];
__device__ __nv_bfloat16 g_B2[(size_t)HID * HID];

__device__ __forceinline__ uint32_t smem_u32(const void* p) {
    uint32_t a;
    asm("{ .reg .u64 t; cvta.to.shared.u64 t, %1; cvt.u32.u64 %0, t; }" : "=r"(a) : "l"(p));
    return a;
}
__device__ __forceinline__ void ldm_x4(uint32_t addr, uint32_t* r) {
    asm volatile("ldmatrix.sync.aligned.m8n8.x4.shared.b16 {%0,%1,%2,%3}, [%4];"
                 : "=r"(r[0]), "=r"(r[1]), "=r"(r[2]), "=r"(r[3]) : "r"(addr));
}
__device__ __forceinline__ void mma_bf16(float* c, const uint32_t* a, const uint32_t* b) {
    asm volatile("mma.sync.aligned.m16n8k16.row.col.f32.bf16.bf16.f32 "
                 "{%0,%1,%2,%3}, {%4,%5,%6,%7}, {%8,%9}, {%0,%1,%2,%3};"
                 : "+f"(c[0]), "+f"(c[1]), "+f"(c[2]), "+f"(c[3])
                 : "r"(a[0]), "r"(a[1]), "r"(a[2]), "r"(a[3]), "r"(b[0]), "r"(b[1]));
}
__device__ __forceinline__ void cp16(uint32_t dst, const void* src) {
    asm volatile("cp.async.cg.shared.global [%0], [%1], 16;" :: "r"(dst), "l"(src));
}
#define CP_COMMIT() asm volatile("cp.async.commit_group;" ::: "memory")
#define CP_WAIT0()  asm volatile("cp.async.wait_group 0;" ::: "memory")

// ---------------- weight prep: W[K,256] fp32 -> gB[256,K] bf16 transposed ----
__global__ void k_prep_B(const float* __restrict__ W, __nv_bfloat16* __restrict__ gB, int K) {
    __shared__ float tile[32][33];
    int t = threadIdx.x;
    int k0 = blockIdx.x * 32, n0 = blockIdx.y * 32;
#pragma unroll
    for (int p = 0; p < 4; p++) {
        int idx = t + 256 * p, i = idx >> 5, j = idx & 31;
        tile[i][j] = W[(size_t)(k0 + i) * HID + n0 + j];
    }
    __syncthreads();
    int jp = t >> 3, i0 = (t & 7) * 4;
    __nv_bfloat16 o[4];
#pragma unroll
    for (int q = 0; q < 4; q++) o[q] = __float2bfloat16(tile[i0 + q][jp]);
    *(uint2*)&gB[(size_t)(n0 + jp) * K + k0 + i0] = *(uint2*)o;
}

// ---------------- GEMM epilogue helper: fp32 acc -> bf16 C ----------------
__device__ __forceinline__ void store_acc_bf16(__nv_bfloat16* C, int HIDc,
                                               float acc[2][8][4], int mo, int wm, int wn,
                                               int lane, int nb) {
#pragma unroll
    for (int mt = 0; mt < 2; mt++) {
        int r0 = mo + wm * 32 + mt * 16 + (lane >> 2);
#pragma unroll
        for (int nt = 0; nt < 8; nt++) {
            int cb = nb + wn * 64 + nt * 8 + (lane & 3) * 2;
            __nv_bfloat162 v0, v1;
            v0.x = __float2bfloat16(acc[mt][nt][0]); v0.y = __float2bfloat16(acc[mt][nt][1]);
            v1.x = __float2bfloat16(acc[mt][nt][2]); v1.y = __float2bfloat16(acc[mt][nt][3]);
            *(__nv_bfloat162*)(C + (size_t)r0 * HIDc + cb)       = v0;
            *(__nv_bfloat162*)(C + (size_t)(r0 + 8) * HIDc + cb) = v1;
        }
    }
}

// ---------------- GEMM (fp32 A): C[M,256] = A @ W ; CTA 128x128, BK=32, 2 CTA/SM ----
#define TILE_BYTES 10240
#define STAGE_BYTES 20480
#define HG_SMEM (2 * STAGE_BYTES)

__global__ __launch_bounds__(256, 2)
void k_hgemm(const float* __restrict__ A, const __nv_bfloat16* __restrict__ gB,
             __nv_bfloat16* __restrict__ C, int K) {
    extern __shared__ char smem[];
    const uint32_t sb = smem_u32(smem);
    const int t = threadIdx.x;
    const int lane = t & 31, w = t >> 5;
    const int wm = w & 3, wn = w >> 2;
    const int mo = blockIdx.x * 128;
    const int nb = blockIdx.y * 128;
    const int nc = K / 32;

    const int arow = t >> 1, acol = (t & 1) * 16;
    const int brow = t >> 1, bpart = t & 1;
    float4 xa[4];

    auto ldgA = [&](int c) {
        const float* Ap = A + (size_t)(mo + arow) * K + c * 32 + acol;
        xa[0] = *(const float4*)(Ap + 0);
        xa[1] = *(const float4*)(Ap + 4);
        xa[2] = *(const float4*)(Ap + 8);
        xa[3] = *(const float4*)(Ap + 12);
    };
    auto cpB = [&](int c, int st) {
        uint32_t dst = sb + st * STAGE_BYTES + TILE_BYTES + brow * 80 + bpart * 32;
        const __nv_bfloat16* Bp = gB + (size_t)(nb + brow) * K + c * 32 + bpart * 16;
        cp16(dst, Bp);
        cp16(dst + 16, Bp + 8);
    };
    auto stsA = [&](int st) {
        char* base = smem + st * STAGE_BYTES;
        __nv_bfloat16 h[16];
#pragma unroll
        for (int q = 0; q < 4; q++) {
            h[q * 4 + 0] = __float2bfloat16(xa[q].x);
            h[q * 4 + 1] = __float2bfloat16(xa[q].y);
            h[q * 4 + 2] = __float2bfloat16(xa[q].z);
            h[q * 4 + 3] = __float2bfloat16(xa[q].w);
        }
        uint32_t aoff = arow * 80 + acol * 2;
        *(uint4*)(base + aoff)      = *(uint4*)&h[0];
        *(uint4*)(base + aoff + 16) = *(uint4*)&h[8];
    };

    float acc[2][8][4];
#pragma unroll
    for (int i = 0; i < 2; i++)
#pragma unroll
        for (int j = 0; j < 8; j++)
#pragma unroll
            for (int e = 0; e < 4; e++) acc[i][j][e] = 0.f;

    const int lm = lane & 7, sel = lane >> 3;
    const uint32_t a_row_off = (uint32_t)(wm * 32 + (sel & 1) * 8 + lm) * 80 + (uint32_t)(sel >> 1) * 16;
    const uint32_t b_row_off = (uint32_t)(wn * 64 + (sel >> 1) * 8 + lm) * 80 + (uint32_t)(sel & 1) * 16;

    cpB(0, 0);
    CP_COMMIT();
    ldgA(0);
    stsA(0);
    CP_WAIT0();
    __syncthreads();

    for (int c = 0; c < nc; c++) {
        const int st = c & 1;
        if (c + 1 < nc) {
            cpB(c + 1, st ^ 1);
            CP_COMMIT();
            ldgA(c + 1);
        }
        const uint32_t stage = sb + st * STAGE_BYTES;
#pragma unroll
        for (int kk = 0; kk < 2; kk++) {
            const uint32_t kb = (uint32_t)kk * 32;
            uint32_t a[2][4];
#pragma unroll
            for (int mt = 0; mt < 2; mt++)
                ldm_x4(stage + a_row_off + (uint32_t)mt * (16 * 80) + kb, a[mt]);
            uint32_t b[8][2];
#pragma unroll
            for (int pr = 0; pr < 4; pr++) {
                uint32_t r[4];
                ldm_x4(stage + TILE_BYTES + b_row_off + (uint32_t)pr * (16 * 80) + kb, r);
                b[2 * pr][0] = r[0]; b[2 * pr][1] = r[1];
                b[2 * pr + 1][0] = r[2]; b[2 * pr + 1][1] = r[3];
            }
#pragma unroll
            for (int mt = 0; mt < 2; mt++)
#pragma unroll
                for (int nt = 0; nt < 8; nt++) mma_bf16(acc[mt][nt], a[mt], b[nt]);
        }
        if (c + 1 < nc) stsA(st ^ 1);
        CP_WAIT0();
        __syncthreads();
    }
    store_acc_bf16(C, HID, acc, mo, wm, wn, lane, nb);
}

// ---------------- GEMM (bf16 A via cp.async): same tiling ----------------
__global__ __launch_bounds__(256, 2)
void k_hgemm_b(const __nv_bfloat16* __restrict__ A, const __nv_bfloat16* __restrict__ gB,
               __nv_bfloat16* __restrict__ C, int K) {
    extern __shared__ char smem[];
    const uint32_t sb = smem_u32(smem);
    const int t = threadIdx.x;
    const int lane = t & 31, w = t >> 5;
    const int wm = w & 3, wn = w >> 2;
    const int mo = blockIdx.x * 128;
    const int nb = blockIdx.y * 128;
    const int nc = K / 32;

    const int arow = t >> 1, apart = t & 1;
    const int brow = t >> 1, bpart = t & 1;

    auto cpAB = [&](int c, int st) {
        uint32_t adst = sb + st * STAGE_BYTES + arow * 80 + apart * 32;
        const __nv_bfloat16* Ap = A + (size_t)(mo + arow) * K + c * 32 + apart * 16;
        cp16(adst, Ap);
        cp16(adst + 16, Ap + 8);
        uint32_t bdst = sb + st * STAGE_BYTES + TILE_BYTES + brow * 80 + bpart * 32;
        const __nv_bfloat16* Bp = gB + (size_t)(nb + brow) * K + c * 32 + bpart * 16;
        cp16(bdst, Bp);
        cp16(bdst + 16, Bp + 8);
    };

    float acc[2][8][4];
#pragma unroll
    for (int i = 0; i < 2; i++)
#pragma unroll
        for (int j = 0; j < 8; j++)
#pragma unroll
            for (int e = 0; e < 4; e++) acc[i][j][e] = 0.f;

    const int lm = lane & 7, sel = lane >> 3;
    const uint32_t a_row_off = (uint32_t)(wm * 32 + (sel & 1) * 8 + lm) * 80 + (uint32_t)(sel >> 1) * 16;
    const uint32_t b_row_off = (uint32_t)(wn * 64 + (sel >> 1) * 8 + lm) * 80 + (uint32_t)(sel & 1) * 16;

    cpAB(0, 0);
    CP_COMMIT();
    CP_WAIT0();
    __syncthreads();

    for (int c = 0; c < nc; c++) {
        const int st = c & 1;
        if (c + 1 < nc) {
            cpAB(c + 1, st ^ 1);
            CP_COMMIT();
        }
        const uint32_t stage = sb + st * STAGE_BYTES;
#pragma unroll
        for (int kk = 0; kk < 2; kk++) {
            const uint32_t kb = (uint32_t)kk * 32;
            uint32_t a[2][4];
#pragma unroll
            for (int mt = 0; mt < 2; mt++)
                ldm_x4(stage + a_row_off + (uint32_t)mt * (16 * 80) + kb, a[mt]);
            uint32_t b[8][2];
#pragma unroll
            for (int pr = 0; pr < 4; pr++) {
                uint32_t r[4];
                ldm_x4(stage + TILE_BYTES + b_row_off + (uint32_t)pr * (16 * 80) + kb, r);
                b[2 * pr][0] = r[0]; b[2 * pr][1] = r[1];
                b[2 * pr + 1][0] = r[2]; b[2 * pr + 1][1] = r[3];
            }
#pragma unroll
            for (int mt = 0; mt < 2; mt++)
#pragma unroll
                for (int nt = 0; nt < 8; nt++) mma_bf16(acc[mt][nt], a[mt], b[nt]);
        }
        CP_WAIT0();
        __syncthreads();
    }
    store_acc_bf16(C, HID, acc, mo, wm, wn, lane, nb);
}

// ---------------- degree / CSR construction ----------------
__global__ void k_init_deg() {
    int i = blockIdx.x * blockDim.x + threadIdx.x;
    if (i < NN) g_deg[i] = 1;
}
__global__ void k_count_deg(const int* __restrict__ dst, int E) {
    int i = blockIdx.x * blockDim.x + threadIdx.x;
    if (i < E) atomicAdd(&g_deg[dst[i]], 1);
}
__global__ void k_dinv() {
    int i = blockIdx.x * blockDim.x + threadIdx.x;
    if (i < NN) g_dinv[i] = rsqrtf((float)g_deg[i]);
}
__global__ void k_scan() {
    __shared__ int sh[1024];
    int tid = threadIdx.x;
    int local[16];
    int sum = 0;
#pragma unroll
    for (int i = 0; i < 16; i++) { local[i] = g_deg[tid * 16 + i]; sum += local[i]; }
    sh[tid] = sum;
    __syncthreads();
    for (int off = 1; off < 1024; off <<= 1) {
        int v = (tid >= off) ? sh[tid - off] : 0;
        __syncthreads();
        sh[tid] += v;
        __syncthreads();
    }
    int run = (tid == 0) ? 0 : sh[tid - 1];
#pragma unroll
    for (int i = 0; i < 16; i++) {
        g_rowstart[tid * 16 + i] = run;
        g_cursor[tid * 16 + i]   = run;
        run += local[i];
    }
    if (tid == 1023) g_rowstart[NN] = run;
}
__global__ void k_fill(const int* __restrict__ src, const int* __restrict__ dst, int E) {
    int i = blockIdx.x * blockDim.x + threadIdx.x;
    if (i >= E + NN) return;
    int s, d;
    if (i < E) { s = src[i]; d = dst[i]; }
    else       { s = i - E; d = s; }
    int slot = atomicAdd(&g_cursor[d], 1);
    g_csr[slot] = s;
}
__global__ void k_sort_rows() {
    __shared__ int s[1024];
    int r = blockIdx.x;
    int beg = g_rowstart[r], end = g_rowstart[r + 1];
    int len = end - beg;
    if (len <= 1 || len > 1024) return;
    for (int i = threadIdx.x; i < len; i += blockDim.x) s[i] = g_csr[beg + i];
    __syncthreads();
    for (int ph = 0; ph < len; ph++) {
        int off = ph & 1;
        for (int j = off + 2 * (int)threadIdx.x; j + 1 < len; j += 2 * (int)blockDim.x) {
            int a = s[j], b = s[j + 1];
            if (a > b) { s[j] = b; s[j + 1] = a; }
        }
        __syncthreads();
    }
    for (int i = threadIdx.x; i < len; i += blockDim.x) g_csr[beg + i] = s[i];
}

// ---------------- aggregation: bf16 in, bf16 out (or fused scores, no store) ----
__global__ void k_agg(const __nv_bfloat16* __restrict__ hin, __nv_bfloat16* __restrict__ hout,
                      const float* __restrict__ bias, const float* __restrict__ linW) {
    int v = blockIdx.x;
    int t = threadIdx.x;
    int beg = g_rowstart[v], end = g_rowstart[v + 1];
    float dv = g_dinv[v];
    __shared__ int   ssrc[256];
    __shared__ float snorm[256];
    __shared__ float red[256];
    float acc = 0.f;
    for (int base = beg; base < end; base += 256) {
        int n = min(256, end - base);
        if (t < n) {
            int s = g_csr[base + t];
            ssrc[t]  = s * HID;
            snorm[t] = g_dinv[s] * dv;
        }
        __syncthreads();
        int j = 0;
        for (; j + 4 <= n; j += 4) {
            float x0 = __bfloat162float(hin[ssrc[j]     + t]);
            float x1 = __bfloat162float(hin[ssrc[j + 1] + t]);
            float x2 = __bfloat162float(hin[ssrc[j + 2] + t]);
            float x3 = __bfloat162float(hin[ssrc[j + 3] + t]);
            acc += x0 * snorm[j] + x1 * snorm[j + 1] + x2 * snorm[j + 2] + x3 * snorm[j + 3];
        }
        for (; j < n; j++) acc += __bfloat162float(hin[ssrc[j] + t]) * snorm[j];
        __syncthreads();
    }
    float r = acc + bias[t];
    r = r > 0.f ? r : 0.f;

    if (hout) hout[(size_t)v * HID + t] = __float2bfloat16(r);

    if (linW) {   // layer-2: produce per-node edge-score partials (no h store needed)
        red[t] = r * linW[t];
        __syncthreads();
        for (int s = 128; s > 0; s >>= 1) {
            if (t < s) red[t] += red[t + s];
            __syncthreads();
        }
        if (t == 0) g_sa[v] = red[0];
        __syncthreads();
        red[t] = r * linW[HID + t];
        __syncthreads();
        for (int s = 128; s > 0; s >>= 1) {
            if (t < s) red[t] += red[t + s];
            __syncthreads();
        }
        if (t == 0) g_sb[v] = red[0];
    }
}

// ---------------- edge scoring ----------------
__global__ void k_edge_out(const int* __restrict__ src, const int* __restrict__ dst,
                           const float* __restrict__ linb, float* __restrict__ out, int E) {
    int i = blockIdx.x * blockDim.x + threadIdx.x;
    if (i < E) out[i] = g_sa[src[i]] + g_sb[dst[i]] + linb[0];
}

// ---------------- launch ----------------
extern "C" void kernel_launch(void* const* d_in, const int* in_sizes, int n_in,
                              void* d_out, int out_size) {
    const float* x    = (const float*)d_in[0];
    const int*   ei   = (const int*)d_in[1];
    const float* W1   = (const float*)d_in[2];
    const float* b1   = (const float*)d_in[3];
    const float* W2   = (const float*)d_in[4];
    const float* b2   = (const float*)d_in[5];
    const float* linW = (const float*)d_in[6];
    const float* linb = (const float*)d_in[7];
    float* out = (float*)d_out;

    int E = in_sizes[1] / 2;
    const int* esrc = ei;
    const int* edst = ei + E;

    __nv_bfloat16 *hb1, *hb2, *B1, *B2;
    cudaGetSymbolAddress((void**)&hb1, g_hb1);
    cudaGetSymbolAddress((void**)&hb2, g_hb2);
    cudaGetSymbolAddress((void**)&B1, g_B1);
    cudaGetSymbolAddress((void**)&B2, g_B2);

    cudaFuncSetAttribute(k_hgemm, cudaFuncAttributeMaxDynamicSharedMemorySize, HG_SMEM);
    cudaFuncSetAttribute(k_hgemm_b, cudaFuncAttributeMaxDynamicSharedMemorySize, HG_SMEM);

    // launch order arranged so k_hgemm (layer 1) is launch index 3 -> ncu captures it
    k_prep_B<<<dim3(NN / 32, HID / 32), 256>>>(W1, B1, NN);          // 0
    k_prep_B<<<dim3(HID / 32, HID / 32), 256>>>(W2, B2, HID);        // 1
    k_init_deg<<<NN / 256, 256>>>();                                 // 2
    k_hgemm<<<dim3(NN / 128, 2), 256, HG_SMEM>>>(x, B1, hb1, NN);    // 3 <- profile target

    // graph structure
    k_count_deg<<<(E + 255) / 256, 256>>>(edst, E);
    k_dinv<<<NN / 256, 256>>>();
    k_scan<<<1, 1024>>>();
    k_fill<<<(E + NN + 255) / 256, 256>>>(esrc, edst, E);
    k_sort_rows<<<NN, 256>>>();

    // layer 1 aggregation: hb1 -> hb2 (bf16)
    k_agg<<<NN, 256>>>(hb1, hb2, b1, (const float*)nullptr);
    // layer 2: GEMM (bf16 A) then agg fused with scores (no h store)
    k_hgemm_b<<<dim3(NN / 128, 2), 256, HG_SMEM>>>(hb2, B2, hb1, HID);
    k_agg<<<NN, 256>>>(hb1, (__nv_bfloat16*)nullptr, b2, linW);

    // edge scores
    k_edge_out<<<(E + 255) / 256, 256>>>(esrc, edst, linb, out, E);
}

// round 14
// speedup vs baseline: 1.1392x; 1.0988x over previous
#include <cuda_runtime.h>
#include <cuda_bf16.h>
#include <cstdint>

#define NN   16384
#define HID  256
#define NEMAX 1048576
#define ETOT (NEMAX + NN)

// ---------------- device scratch ----------------
__device__ __nv_bfloat16 g_hb1[(size_t)NN * HID];  // GEMM outputs (bf16)
__device__ __nv_bfloat16 g_hb2[(size_t)NN * HID];  // agg1 output (bf16) = GEMM2 A
__device__ int   g_deg[NN];
__device__ float g_dinv[NN];
__device__ int   g_rowstart[NN + 1];
__device__ int   g_cursor[NN];
__device__ int   g_csr[ETOT];
__device__ float g_sa[NN];
__device__ float g_sb[NN];
__device__ __nv_bfloat16 g_B1[(size_t)HID * NN];
__device__ __nv_bfloat16 g_B2[(size_t)HID * HID];

__device__ __forceinline__ uint32_t smem_u32(const void* p) {
    uint32_t a;
    asm("{ .reg .u64 t; cvta.to.shared.u64 t, %1; cvt.u32.u64 %0, t; }" : "=r"(a) : "l"(p));
    return a;
}
__device__ __forceinline__ void ldm_x4(uint32_t addr, uint32_t* r) {
    asm volatile("ldmatrix.sync.aligned.m8n8.x4.shared.b16 {%0,%1,%2,%3}, [%4];"
                 : "=r"(r[0]), "=r"(r[1]), "=r"(r[2]), "=r"(r[3]) : "r"(addr));
}
__device__ __forceinline__ void mma_bf16(float* c, const uint32_t* a, const uint32_t* b) {
    asm volatile("mma.sync.aligned.m16n8k16.row.col.f32.bf16.bf16.f32 "
                 "{%0,%1,%2,%3}, {%4,%5,%6,%7}, {%8,%9}, {%0,%1,%2,%3};"
                 : "+f"(c[0]), "+f"(c[1]), "+f"(c[2]), "+f"(c[3])
                 : "r"(a[0]), "r"(a[1]), "r"(a[2]), "r"(a[3]), "r"(b[0]), "r"(b[1]));
}
__device__ __forceinline__ void cp16(uint32_t dst, const void* src) {
    asm volatile("cp.async.cg.shared.global [%0], [%1], 16;" :: "r"(dst), "l"(src));
}
#define CP_COMMIT() asm volatile("cp.async.commit_group;" ::: "memory")
#define CP_WAIT0()  asm volatile("cp.async.wait_group 0;" ::: "memory")

// ---------------- weight prep ----------------
__global__ void k_prep_B(const float* __restrict__ W, __nv_bfloat16* __restrict__ gB, int K) {
    __shared__ float tile[32][33];
    int t = threadIdx.x;
    int k0 = blockIdx.x * 32, n0 = blockIdx.y * 32;
#pragma unroll
    for (int p = 0; p < 4; p++) {
        int idx = t + 256 * p, i = idx >> 5, j = idx & 31;
        tile[i][j] = W[(size_t)(k0 + i) * HID + n0 + j];
    }
    __syncthreads();
    int jp = t >> 3, i0 = (t & 7) * 4;
    __nv_bfloat16 o[4];
#pragma unroll
    for (int q = 0; q < 4; q++) o[q] = __float2bfloat16(tile[i0 + q][jp]);
    *(uint2*)&gB[(size_t)(n0 + jp) * K + k0 + i0] = *(uint2*)o;
}

// ---------------- GEMM epilogue helper ----------------
__device__ __forceinline__ void store_acc_bf16(__nv_bfloat16* C, int HIDc,
                                               float acc[2][8][4], int mo, int wm, int wn,
                                               int lane, int nb) {
#pragma unroll
    for (int mt = 0; mt < 2; mt++) {
        int r0 = mo + wm * 32 + mt * 16 + (lane >> 2);
#pragma unroll
        for (int nt = 0; nt < 8; nt++) {
            int cb = nb + wn * 64 + nt * 8 + (lane & 3) * 2;
            __nv_bfloat162 v0, v1;
            v0.x = __float2bfloat16(acc[mt][nt][0]); v0.y = __float2bfloat16(acc[mt][nt][1]);
            v1.x = __float2bfloat16(acc[mt][nt][2]); v1.y = __float2bfloat16(acc[mt][nt][3]);
            *(__nv_bfloat162*)(C + (size_t)r0 * HIDc + cb)       = v0;
            *(__nv_bfloat162*)(C + (size_t)(r0 + 8) * HIDc + cb) = v1;
        }
    }
}

// ---------------- GEMM (fp32 A): CTA 128x128, BK=32, 2 CTA/SM ----------------
#define TILE_BYTES 10240
#define STAGE_BYTES 20480
#define HG_SMEM (2 * STAGE_BYTES)

__global__ __launch_bounds__(256, 2)
void k_hgemm(const float* __restrict__ A, const __nv_bfloat16* __restrict__ gB,
             __nv_bfloat16* __restrict__ C, int K) {
    extern __shared__ char smem[];
    const uint32_t sb = smem_u32(smem);
    const int t = threadIdx.x;
    const int lane = t & 31, w = t >> 5;
    const int wm = w & 3, wn = w >> 2;
    const int mo = blockIdx.x * 128;
    const int nb = blockIdx.y * 128;
    const int nc = K / 32;

    const int arow = t >> 1, acol = (t & 1) * 16;
    const int brow = t >> 1, bpart = t & 1;
    float4 xa[4];

    auto ldgA = [&](int c) {
        const float* Ap = A + (size_t)(mo + arow) * K + c * 32 + acol;
        xa[0] = *(const float4*)(Ap + 0);
        xa[1] = *(const float4*)(Ap + 4);
        xa[2] = *(const float4*)(Ap + 8);
        xa[3] = *(const float4*)(Ap + 12);
    };
    auto cpB = [&](int c, int st) {
        uint32_t dst = sb + st * STAGE_BYTES + TILE_BYTES + brow * 80 + bpart * 32;
        const __nv_bfloat16* Bp = gB + (size_t)(nb + brow) * K + c * 32 + bpart * 16;
        cp16(dst, Bp);
        cp16(dst + 16, Bp + 8);
    };
    auto stsA = [&](int st) {
        char* base = smem + st * STAGE_BYTES;
        __nv_bfloat16 h[16];
#pragma unroll
        for (int q = 0; q < 4; q++) {
            h[q * 4 + 0] = __float2bfloat16(xa[q].x);
            h[q * 4 + 1] = __float2bfloat16(xa[q].y);
            h[q * 4 + 2] = __float2bfloat16(xa[q].z);
            h[q * 4 + 3] = __float2bfloat16(xa[q].w);
        }
        uint32_t aoff = arow * 80 + acol * 2;
        *(uint4*)(base + aoff)      = *(uint4*)&h[0];
        *(uint4*)(base + aoff + 16) = *(uint4*)&h[8];
    };

    float acc[2][8][4];
#pragma unroll
    for (int i = 0; i < 2; i++)
#pragma unroll
        for (int j = 0; j < 8; j++)
#pragma unroll
            for (int e = 0; e < 4; e++) acc[i][j][e] = 0.f;

    const int lm = lane & 7, sel = lane >> 3;
    const uint32_t a_row_off = (uint32_t)(wm * 32 + (sel & 1) * 8 + lm) * 80 + (uint32_t)(sel >> 1) * 16;
    const uint32_t b_row_off = (uint32_t)(wn * 64 + (sel >> 1) * 8 + lm) * 80 + (uint32_t)(sel & 1) * 16;

    cpB(0, 0);
    CP_COMMIT();
    ldgA(0);
    stsA(0);
    CP_WAIT0();
    __syncthreads();

    for (int c = 0; c < nc; c++) {
        const int st = c & 1;
        if (c + 1 < nc) {
            cpB(c + 1, st ^ 1);
            CP_COMMIT();
            ldgA(c + 1);
        }
        const uint32_t stage = sb + st * STAGE_BYTES;
#pragma unroll
        for (int kk = 0; kk < 2; kk++) {
            const uint32_t kb = (uint32_t)kk * 32;
            uint32_t a[2][4];
#pragma unroll
            for (int mt = 0; mt < 2; mt++)
                ldm_x4(stage + a_row_off + (uint32_t)mt * (16 * 80) + kb, a[mt]);
            uint32_t b[8][2];
#pragma unroll
            for (int pr = 0; pr < 4; pr++) {
                uint32_t r[4];
                ldm_x4(stage + TILE_BYTES + b_row_off + (uint32_t)pr * (16 * 80) + kb, r);
                b[2 * pr][0] = r[0]; b[2 * pr][1] = r[1];
                b[2 * pr + 1][0] = r[2]; b[2 * pr + 1][1] = r[3];
            }
#pragma unroll
            for (int mt = 0; mt < 2; mt++)
#pragma unroll
                for (int nt = 0; nt < 8; nt++) mma_bf16(acc[mt][nt], a[mt], b[nt]);
        }
        if (c + 1 < nc) stsA(st ^ 1);
        CP_WAIT0();
        __syncthreads();
    }
    store_acc_bf16(C, HID, acc, mo, wm, wn, lane, nb);
}

// ---------------- GEMM (bf16 A via cp.async) ----------------
__global__ __launch_bounds__(256, 2)
void k_hgemm_b(const __nv_bfloat16* __restrict__ A, const __nv_bfloat16* __restrict__ gB,
               __nv_bfloat16* __restrict__ C, int K) {
    extern __shared__ char smem[];
    const uint32_t sb = smem_u32(smem);
    const int t = threadIdx.x;
    const int lane = t & 31, w = t >> 5;
    const int wm = w & 3, wn = w >> 2;
    const int mo = blockIdx.x * 128;
    const int nb = blockIdx.y * 128;
    const int nc = K / 32;

    const int arow = t >> 1, apart = t & 1;
    const int brow = t >> 1, bpart = t & 1;

    auto cpAB = [&](int c, int st) {
        uint32_t adst = sb + st * STAGE_BYTES + arow * 80 + apart * 32;
        const __nv_bfloat16* Ap = A + (size_t)(mo + arow) * K + c * 32 + apart * 16;
        cp16(adst, Ap);
        cp16(adst + 16, Ap + 8);
        uint32_t bdst = sb + st * STAGE_BYTES + TILE_BYTES + brow * 80 + bpart * 32;
        const __nv_bfloat16* Bp = gB + (size_t)(nb + brow) * K + c * 32 + bpart * 16;
        cp16(bdst, Bp);
        cp16(bdst + 16, Bp + 8);
    };

    float acc[2][8][4];
#pragma unroll
    for (int i = 0; i < 2; i++)
#pragma unroll
        for (int j = 0; j < 8; j++)
#pragma unroll
            for (int e = 0; e < 4; e++) acc[i][j][e] = 0.f;

    const int lm = lane & 7, sel = lane >> 3;
    const uint32_t a_row_off = (uint32_t)(wm * 32 + (sel & 1) * 8 + lm) * 80 + (uint32_t)(sel >> 1) * 16;
    const uint32_t b_row_off = (uint32_t)(wn * 64 + (sel >> 1) * 8 + lm) * 80 + (uint32_t)(sel & 1) * 16;

    cpAB(0, 0);
    CP_COMMIT();
    CP_WAIT0();
    __syncthreads();

    for (int c = 0; c < nc; c++) {
        const int st = c & 1;
        if (c + 1 < nc) {
            cpAB(c + 1, st ^ 1);
            CP_COMMIT();
        }
        const uint32_t stage = sb + st * STAGE_BYTES;
#pragma unroll
        for (int kk = 0; kk < 2; kk++) {
            const uint32_t kb = (uint32_t)kk * 32;
            uint32_t a[2][4];
#pragma unroll
            for (int mt = 0; mt < 2; mt++)
                ldm_x4(stage + a_row_off + (uint32_t)mt * (16 * 80) + kb, a[mt]);
            uint32_t b[8][2];
#pragma unroll
            for (int pr = 0; pr < 4; pr++) {
                uint32_t r[4];
                ldm_x4(stage + TILE_BYTES + b_row_off + (uint32_t)pr * (16 * 80) + kb, r);
                b[2 * pr][0] = r[0]; b[2 * pr][1] = r[1];
                b[2 * pr + 1][0] = r[2]; b[2 * pr + 1][1] = r[3];
            }
#pragma unroll
            for (int mt = 0; mt < 2; mt++)
#pragma unroll
                for (int nt = 0; nt < 8; nt++) mma_bf16(acc[mt][nt], a[mt], b[nt]);
        }
        CP_WAIT0();
        __syncthreads();
    }
    store_acc_bf16(C, HID, acc, mo, wm, wn, lane, nb);
}

// ---------------- degree / CSR construction ----------------
__global__ void k_init_deg() {
    int i = blockIdx.x * blockDim.x + threadIdx.x;
    if (i < NN) g_deg[i] = 1;
}
__global__ void k_count_deg(const int* __restrict__ dst, int E) {
    int i = blockIdx.x * blockDim.x + threadIdx.x;
    if (i < E) atomicAdd(&g_deg[dst[i]], 1);
}
// scan + dinv fused (single block)
__global__ void k_scan() {
    __shared__ int sh[1024];
    int tid = threadIdx.x;
    int local[16];
    int sum = 0;
#pragma unroll
    for (int i = 0; i < 16; i++) {
        int d = g_deg[tid * 16 + i];
        local[i] = d;
        g_dinv[tid * 16 + i] = rsqrtf((float)d);
        sum += d;
    }
    sh[tid] = sum;
    __syncthreads();
    for (int off = 1; off < 1024; off <<= 1) {
        int v = (tid >= off) ? sh[tid - off] : 0;
        __syncthreads();
        sh[tid] += v;
        __syncthreads();
    }
    int run = (tid == 0) ? 0 : sh[tid - 1];
#pragma unroll
    for (int i = 0; i < 16; i++) {
        g_rowstart[tid * 16 + i] = run;
        g_cursor[tid * 16 + i]   = run;
        run += local[i];
    }
    if (tid == 1023) g_rowstart[NN] = run;
}
__global__ void k_fill(const int* __restrict__ src, const int* __restrict__ dst, int E) {
    int i = blockIdx.x * blockDim.x + threadIdx.x;
    if (i >= E + NN) return;
    int s, d;
    if (i < E) { s = src[i]; d = dst[i]; }
    else       { s = i - E; d = s; }
    int slot = atomicAdd(&g_cursor[d], 1);
    g_csr[slot] = s;
}
__global__ void k_sort_rows() {
    __shared__ int s[1024];
    int r = blockIdx.x;
    int beg = g_rowstart[r], end = g_rowstart[r + 1];
    int len = end - beg;
    if (len <= 1 || len > 1024) return;
    for (int i = threadIdx.x; i < len; i += blockDim.x) s[i] = g_csr[beg + i];
    __syncthreads();
    for (int ph = 0; ph < len; ph++) {
        int off = ph & 1;
        for (int j = off + 2 * (int)threadIdx.x; j + 1 < len; j += 2 * (int)blockDim.x) {
            int a = s[j], b = s[j + 1];
            if (a > b) { s[j] = b; s[j + 1] = a; }
        }
        __syncthreads();
    }
    for (int i = threadIdx.x; i < len; i += blockDim.x) g_csr[beg + i] = s[i];
}

// ---------------- aggregation: 4 neighbors in parallel, 8B loads ----------------
// t = g*64 + cg : g = neighbor sub-lane (0..3), cg = column group (4 bf16 cols).
__global__ void k_agg(const __nv_bfloat16* __restrict__ hin, __nv_bfloat16* __restrict__ hout,
                      const float* __restrict__ bias, const float* __restrict__ linW) {
    int v = blockIdx.x;
    int t = threadIdx.x;
    int g = t >> 6;
    int cg = t & 63;
    int beg = g_rowstart[v], end = g_rowstart[v + 1];
    float dv = g_dinv[v];
    __shared__ int   ssrc[256];
    __shared__ float snorm[256];
    __shared__ float4 red4[3][64];
    __shared__ float reda[64], redb[64];

    float4 acc = make_float4(0.f, 0.f, 0.f, 0.f);
    for (int base = beg; base < end; base += 256) {
        int n = min(256, end - base);
        if (t < n) {
            int s = g_csr[base + t];
            ssrc[t]  = s * HID;
            snorm[t] = g_dinv[s] * dv;
        }
        __syncthreads();
        for (int j = g; j < n; j += 4) {
            uint2 raw = *(const uint2*)(hin + ssrc[j] + cg * 4);
            float wgt = snorm[j];
            __nv_bfloat162 p0 = *(__nv_bfloat162*)&raw.x;
            __nv_bfloat162 p1 = *(__nv_bfloat162*)&raw.y;
            float2 f0 = __bfloat1622float2(p0);
            float2 f1 = __bfloat1622float2(p1);
            acc.x += f0.x * wgt;
            acc.y += f0.y * wgt;
            acc.z += f1.x * wgt;
            acc.w += f1.y * wgt;
        }
        __syncthreads();
    }
    if (g > 0) red4[g - 1][cg] = acc;
    __syncthreads();
    if (t < 64) {
        float4 a = red4[0][t], b = red4[1][t], c = red4[2][t];
        float r0 = acc.x + a.x + b.x + c.x + bias[t * 4 + 0];
        float r1 = acc.y + a.y + b.y + c.y + bias[t * 4 + 1];
        float r2 = acc.z + a.z + b.z + c.z + bias[t * 4 + 2];
        float r3 = acc.w + a.w + b.w + c.w + bias[t * 4 + 3];
        r0 = r0 > 0.f ? r0 : 0.f;
        r1 = r1 > 0.f ? r1 : 0.f;
        r2 = r2 > 0.f ? r2 : 0.f;
        r3 = r3 > 0.f ? r3 : 0.f;
        if (hout) {
            __nv_bfloat16 o[4] = {__float2bfloat16(r0), __float2bfloat16(r1),
                                  __float2bfloat16(r2), __float2bfloat16(r3)};
            *(uint2*)(hout + (size_t)v * HID + t * 4) = *(uint2*)o;
        }
        if (linW) {
            reda[t] = r0 * linW[t*4] + r1 * linW[t*4+1] + r2 * linW[t*4+2] + r3 * linW[t*4+3];
            redb[t] = r0 * linW[HID + t*4]     + r1 * linW[HID + t*4+1]
                    + r2 * linW[HID + t*4+2]   + r3 * linW[HID + t*4+3];
        }
    }
    if (linW) {
        __syncthreads();
        if (t < 32) {
            float a = reda[t] + reda[t + 32];
            float b = redb[t] + redb[t + 32];
#pragma unroll
            for (int off = 16; off > 0; off >>= 1) {
                a += __shfl_down_sync(0xffffffffu, a, off);
                b += __shfl_down_sync(0xffffffffu, b, off);
            }
            if (t == 0) { g_sa[v] = a; g_sb[v] = b; }
        }
    }
}

// ---------------- edge scoring ----------------
__global__ void k_edge_out(const int* __restrict__ src, const int* __restrict__ dst,
                           const float* __restrict__ linb, float* __restrict__ out, int E) {
    int i = blockIdx.x * blockDim.x + threadIdx.x;
    if (i < E) out[i] = g_sa[src[i]] + g_sb[dst[i]] + linb[0];
}

// ---------------- launch ----------------
extern "C" void kernel_launch(void* const* d_in, const int* in_sizes, int n_in,
                              void* d_out, int out_size) {
    const float* x    = (const float*)d_in[0];
    const int*   ei   = (const int*)d_in[1];
    const float* W1   = (const float*)d_in[2];
    const float* b1   = (const float*)d_in[3];
    const float* W2   = (const float*)d_in[4];
    const float* b2   = (const float*)d_in[5];
    const float* linW = (const float*)d_in[6];
    const float* linb = (const float*)d_in[7];
    float* out = (float*)d_out;

    int E = in_sizes[1] / 2;
    const int* esrc = ei;
    const int* edst = ei + E;

    __nv_bfloat16 *hb1, *hb2, *B1, *B2;
    cudaGetSymbolAddress((void**)&hb1, g_hb1);
    cudaGetSymbolAddress((void**)&hb2, g_hb2);
    cudaGetSymbolAddress((void**)&B1, g_B1);
    cudaGetSymbolAddress((void**)&B2, g_B2);

    cudaFuncSetAttribute(k_hgemm, cudaFuncAttributeMaxDynamicSharedMemorySize, HG_SMEM);
    cudaFuncSetAttribute(k_hgemm_b, cudaFuncAttributeMaxDynamicSharedMemorySize, HG_SMEM);

    // launch order arranged so k_hgemm (layer 1) is launch index 3 -> ncu captures it
    k_prep_B<<<dim3(NN / 32, HID / 32), 256>>>(W1, B1, NN);          // 0
    k_prep_B<<<dim3(HID / 32, HID / 32), 256>>>(W2, B2, HID);        // 1
    k_init_deg<<<NN / 256, 256>>>();                                 // 2
    k_hgemm<<<dim3(NN / 128, 2), 256, HG_SMEM>>>(x, B1, hb1, NN);    // 3 <- profile target

    // graph structure
    k_count_deg<<<(E + 255) / 256, 256>>>(edst, E);
    k_scan<<<1, 1024>>>();
    k_fill<<<(E + NN + 255) / 256, 256>>>(esrc, edst, E);
    k_sort_rows<<<NN, 256>>>();

    // layer 1 aggregation: hb1 -> hb2 (bf16)
    k_agg<<<NN, 256>>>(hb1, hb2, b1, (const float*)nullptr);
    // layer 2: GEMM (bf16 A) then agg fused with scores (no h store)
    k_hgemm_b<<<dim3(NN / 128, 2), 256, HG_SMEM>>>(hb2, B2, hb1, HID);
    k_agg<<<NN, 256>>>(hb1, (__nv_bfloat16*)nullptr, b2, linW);

    // edge scores
    k_edge_out<<<(E + 255) / 256, 256>>>(esrc, edst, linb, out, E);
}

// round 15
// speedup vs baseline: 1.3762x; 1.2080x over previous
#include <cuda_runtime.h>
#include <cuda_bf16.h>
#include <cstdint>

#define NN   16384
#define HID  256
#define NEMAX 1048576
#define ETOT (NEMAX + NN)

// ---------------- device scratch ----------------
__device__ __nv_bfloat16 g_hb1[(size_t)NN * HID];
__device__ __nv_bfloat16 g_hb2[(size_t)NN * HID];
__device__ int   g_deg[NN];
__device__ float g_dinv[NN];
__device__ int   g_rowstart[NN + 1];
__device__ int   g_cursor[NN];
__device__ int   g_csr[ETOT];
__device__ float g_sa[NN];
__device__ float g_sb[NN];
__device__ __nv_bfloat16 g_B1[(size_t)HID * NN];
__device__ __nv_bfloat16 g_B2[(size_t)HID * HID];

__device__ __forceinline__ uint32_t smem_u32(const void* p) {
    uint32_t a;
    asm("{ .reg .u64 t; cvta.to.shared.u64 t, %1; cvt.u32.u64 %0, t; }" : "=r"(a) : "l"(p));
    return a;
}
__device__ __forceinline__ void ldm_x4(uint32_t addr, uint32_t* r) {
    asm volatile("ldmatrix.sync.aligned.m8n8.x4.shared.b16 {%0,%1,%2,%3}, [%4];"
                 : "=r"(r[0]), "=r"(r[1]), "=r"(r[2]), "=r"(r[3]) : "r"(addr));
}
__device__ __forceinline__ void mma_bf16(float* c, const uint32_t* a, const uint32_t* b) {
    asm volatile("mma.sync.aligned.m16n8k16.row.col.f32.bf16.bf16.f32 "
                 "{%0,%1,%2,%3}, {%4,%5,%6,%7}, {%8,%9}, {%0,%1,%2,%3};"
                 : "+f"(c[0]), "+f"(c[1]), "+f"(c[2]), "+f"(c[3])
                 : "r"(a[0]), "r"(a[1]), "r"(a[2]), "r"(a[3]), "r"(b[0]), "r"(b[1]));
}
__device__ __forceinline__ void cp16(uint32_t dst, const void* src) {
    asm volatile("cp.async.cg.shared.global [%0], [%1], 16;" :: "r"(dst), "l"(src));
}
#define CP_COMMIT() asm volatile("cp.async.commit_group;" ::: "memory")
#define CP_WAIT0()  asm volatile("cp.async.wait_group 0;" ::: "memory")

// ---------------- weight prep ----------------
__global__ void k_prep_B(const float* __restrict__ W, __nv_bfloat16* __restrict__ gB, int K) {
    __shared__ float tile[32][33];
    int t = threadIdx.x;
    int k0 = blockIdx.x * 32, n0 = blockIdx.y * 32;
#pragma unroll
    for (int p = 0; p < 4; p++) {
        int idx = t + 256 * p, i = idx >> 5, j = idx & 31;
        tile[i][j] = W[(size_t)(k0 + i) * HID + n0 + j];
    }
    __syncthreads();
    int jp = t >> 3, i0 = (t & 7) * 4;
    __nv_bfloat16 o[4];
#pragma unroll
    for (int q = 0; q < 4; q++) o[q] = __float2bfloat16(tile[i0 + q][jp]);
    *(uint2*)&gB[(size_t)(n0 + jp) * K + k0 + i0] = *(uint2*)o;
}

// ---------------- GEMM epilogue helper ----------------
__device__ __forceinline__ void store_acc_bf16(__nv_bfloat16* C, int HIDc,
                                               float acc[2][8][4], int mo, int wm, int wn,
                                               int lane, int nb) {
#pragma unroll
    for (int mt = 0; mt < 2; mt++) {
        int r0 = mo + wm * 32 + mt * 16 + (lane >> 2);
#pragma unroll
        for (int nt = 0; nt < 8; nt++) {
            int cb = nb + wn * 64 + nt * 8 + (lane & 3) * 2;
            __nv_bfloat162 v0, v1;
            v0.x = __float2bfloat16(acc[mt][nt][0]); v0.y = __float2bfloat16(acc[mt][nt][1]);
            v1.x = __float2bfloat16(acc[mt][nt][2]); v1.y = __float2bfloat16(acc[mt][nt][3]);
            *(__nv_bfloat162*)(C + (size_t)r0 * HIDc + cb)       = v0;
            *(__nv_bfloat162*)(C + (size_t)(r0 + 8) * HIDc + cb) = v1;
        }
    }
}

// ---------------- GEMM (fp32 A): CTA 128x128, BK=32, 2 CTA/SM ----------------
#define TILE_BYTES 10240
#define STAGE_BYTES 20480
#define HG_SMEM (2 * STAGE_BYTES)

__global__ __launch_bounds__(256, 2)
void k_hgemm(const float* __restrict__ A, const __nv_bfloat16* __restrict__ gB,
             __nv_bfloat16* __restrict__ C, int K) {
    extern __shared__ char smem[];
    const uint32_t sb = smem_u32(smem);
    const int t = threadIdx.x;
    const int lane = t & 31, w = t >> 5;
    const int wm = w & 3, wn = w >> 2;
    const int mo = blockIdx.x * 128;
    const int nb = blockIdx.y * 128;
    const int nc = K / 32;

    const int arow = t >> 1, acol = (t & 1) * 16;
    const int brow = t >> 1, bpart = t & 1;
    float4 xa[4];

    auto ldgA = [&](int c) {
        const float* Ap = A + (size_t)(mo + arow) * K + c * 32 + acol;
        xa[0] = *(const float4*)(Ap + 0);
        xa[1] = *(const float4*)(Ap + 4);
        xa[2] = *(const float4*)(Ap + 8);
        xa[3] = *(const float4*)(Ap + 12);
    };
    auto cpB = [&](int c, int st) {
        uint32_t dst = sb + st * STAGE_BYTES + TILE_BYTES + brow * 80 + bpart * 32;
        const __nv_bfloat16* Bp = gB + (size_t)(nb + brow) * K + c * 32 + bpart * 16;
        cp16(dst, Bp);
        cp16(dst + 16, Bp + 8);
    };
    auto stsA = [&](int st) {
        char* base = smem + st * STAGE_BYTES;
        __nv_bfloat16 h[16];
#pragma unroll
        for (int q = 0; q < 4; q++) {
            h[q * 4 + 0] = __float2bfloat16(xa[q].x);
            h[q * 4 + 1] = __float2bfloat16(xa[q].y);
            h[q * 4 + 2] = __float2bfloat16(xa[q].z);
            h[q * 4 + 3] = __float2bfloat16(xa[q].w);
        }
        uint32_t aoff = arow * 80 + acol * 2;
        *(uint4*)(base + aoff)      = *(uint4*)&h[0];
        *(uint4*)(base + aoff + 16) = *(uint4*)&h[8];
    };

    float acc[2][8][4];
#pragma unroll
    for (int i = 0; i < 2; i++)
#pragma unroll
        for (int j = 0; j < 8; j++)
#pragma unroll
            for (int e = 0; e < 4; e++) acc[i][j][e] = 0.f;

    const int lm = lane & 7, sel = lane >> 3;
    const uint32_t a_row_off = (uint32_t)(wm * 32 + (sel & 1) * 8 + lm) * 80 + (uint32_t)(sel >> 1) * 16;
    const uint32_t b_row_off = (uint32_t)(wn * 64 + (sel >> 1) * 8 + lm) * 80 + (uint32_t)(sel & 1) * 16;

    cpB(0, 0);
    CP_COMMIT();
    ldgA(0);
    stsA(0);
    CP_WAIT0();
    __syncthreads();

    for (int c = 0; c < nc; c++) {
        const int st = c & 1;
        if (c + 1 < nc) {
            cpB(c + 1, st ^ 1);
            CP_COMMIT();
            ldgA(c + 1);
        }
        const uint32_t stage = sb + st * STAGE_BYTES;
#pragma unroll
        for (int kk = 0; kk < 2; kk++) {
            const uint32_t kb = (uint32_t)kk * 32;
            uint32_t a[2][4];
#pragma unroll
            for (int mt = 0; mt < 2; mt++)
                ldm_x4(stage + a_row_off + (uint32_t)mt * (16 * 80) + kb, a[mt]);
            uint32_t b[8][2];
#pragma unroll
            for (int pr = 0; pr < 4; pr++) {
                uint32_t r[4];
                ldm_x4(stage + TILE_BYTES + b_row_off + (uint32_t)pr * (16 * 80) + kb, r);
                b[2 * pr][0] = r[0]; b[2 * pr][1] = r[1];
                b[2 * pr + 1][0] = r[2]; b[2 * pr + 1][1] = r[3];
            }
#pragma unroll
            for (int mt = 0; mt < 2; mt++)
#pragma unroll
                for (int nt = 0; nt < 8; nt++) mma_bf16(acc[mt][nt], a[mt], b[nt]);
        }
        if (c + 1 < nc) stsA(st ^ 1);
        CP_WAIT0();
        __syncthreads();
    }
    store_acc_bf16(C, HID, acc, mo, wm, wn, lane, nb);
}

// ---------------- GEMM (bf16 A via cp.async) ----------------
__global__ __launch_bounds__(256, 2)
void k_hgemm_b(const __nv_bfloat16* __restrict__ A, const __nv_bfloat16* __restrict__ gB,
               __nv_bfloat16* __restrict__ C, int K) {
    extern __shared__ char smem[];
    const uint32_t sb = smem_u32(smem);
    const int t = threadIdx.x;
    const int lane = t & 31, w = t >> 5;
    const int wm = w & 3, wn = w >> 2;
    const int mo = blockIdx.x * 128;
    const int nb = blockIdx.y * 128;
    const int nc = K / 32;

    const int arow = t >> 1, apart = t & 1;
    const int brow = t >> 1, bpart = t & 1;

    auto cpAB = [&](int c, int st) {
        uint32_t adst = sb + st * STAGE_BYTES + arow * 80 + apart * 32;
        const __nv_bfloat16* Ap = A + (size_t)(mo + arow) * K + c * 32 + apart * 16;
        cp16(adst, Ap);
        cp16(adst + 16, Ap + 8);
        uint32_t bdst = sb + st * STAGE_BYTES + TILE_BYTES + brow * 80 + bpart * 32;
        const __nv_bfloat16* Bp = gB + (size_t)(nb + brow) * K + c * 32 + bpart * 16;
        cp16(bdst, Bp);
        cp16(bdst + 16, Bp + 8);
    };

    float acc[2][8][4];
#pragma unroll
    for (int i = 0; i < 2; i++)
#pragma unroll
        for (int j = 0; j < 8; j++)
#pragma unroll
            for (int e = 0; e < 4; e++) acc[i][j][e] = 0.f;

    const int lm = lane & 7, sel = lane >> 3;
    const uint32_t a_row_off = (uint32_t)(wm * 32 + (sel & 1) * 8 + lm) * 80 + (uint32_t)(sel >> 1) * 16;
    const uint32_t b_row_off = (uint32_t)(wn * 64 + (sel >> 1) * 8 + lm) * 80 + (uint32_t)(sel & 1) * 16;

    cpAB(0, 0);
    CP_COMMIT();
    CP_WAIT0();
    __syncthreads();

    for (int c = 0; c < nc; c++) {
        const int st = c & 1;
        if (c + 1 < nc) {
            cpAB(c + 1, st ^ 1);
            CP_COMMIT();
        }
        const uint32_t stage = sb + st * STAGE_BYTES;
#pragma unroll
        for (int kk = 0; kk < 2; kk++) {
            const uint32_t kb = (uint32_t)kk * 32;
            uint32_t a[2][4];
#pragma unroll
            for (int mt = 0; mt < 2; mt++)
                ldm_x4(stage + a_row_off + (uint32_t)mt * (16 * 80) + kb, a[mt]);
            uint32_t b[8][2];
#pragma unroll
            for (int pr = 0; pr < 4; pr++) {
                uint32_t r[4];
                ldm_x4(stage + TILE_BYTES + b_row_off + (uint32_t)pr * (16 * 80) + kb, r);
                b[2 * pr][0] = r[0]; b[2 * pr][1] = r[1];
                b[2 * pr + 1][0] = r[2]; b[2 * pr + 1][1] = r[3];
            }
#pragma unroll
            for (int mt = 0; mt < 2; mt++)
#pragma unroll
                for (int nt = 0; nt < 8; nt++) mma_bf16(acc[mt][nt], a[mt], b[nt]);
        }
        CP_WAIT0();
        __syncthreads();
    }
    store_acc_bf16(C, HID, acc, mo, wm, wn, lane, nb);
}

// ---------------- degree / CSR construction ----------------
__global__ void k_init_deg() {
    int i = blockIdx.x * blockDim.x + threadIdx.x;
    if (i < NN) g_deg[i] = 1;
}
__global__ void k_count_deg(const int* __restrict__ dst, int E) {
    int i = blockIdx.x * blockDim.x + threadIdx.x;
    if (i < E) atomicAdd(&g_deg[dst[i]], 1);
}
__global__ void k_scan() {
    __shared__ int sh[1024];
    int tid = threadIdx.x;
    int local[16];
    int sum = 0;
#pragma unroll
    for (int i = 0; i < 16; i++) {
        int d = g_deg[tid * 16 + i];
        local[i] = d;
        g_dinv[tid * 16 + i] = rsqrtf((float)d);
        sum += d;
    }
    sh[tid] = sum;
    __syncthreads();
    for (int off = 1; off < 1024; off <<= 1) {
        int v = (tid >= off) ? sh[tid - off] : 0;
        __syncthreads();
        sh[tid] += v;
        __syncthreads();
    }
    int run = (tid == 0) ? 0 : sh[tid - 1];
#pragma unroll
    for (int i = 0; i < 16; i++) {
        g_rowstart[tid * 16 + i] = run;
        g_cursor[tid * 16 + i]   = run;
        run += local[i];
    }
    if (tid == 1023) g_rowstart[NN] = run;
}
__global__ void k_fill(const int* __restrict__ src, const int* __restrict__ dst, int E) {
    int i = blockIdx.x * blockDim.x + threadIdx.x;
    if (i >= E + NN) return;
    int s, d;
    if (i < E) { s = src[i]; d = dst[i]; }
    else       { s = i - E; d = s; }
    int slot = atomicAdd(&g_cursor[d], 1);
    g_csr[slot] = s;
}
__global__ void k_sort_rows() {
    __shared__ int s[1024];
    int r = blockIdx.x;
    int beg = g_rowstart[r], end = g_rowstart[r + 1];
    int len = end - beg;
    if (len <= 1 || len > 1024) return;
    for (int i = threadIdx.x; i < len; i += blockDim.x) s[i] = g_csr[beg + i];
    __syncthreads();
    for (int ph = 0; ph < len; ph++) {
        int off = ph & 1;
        for (int j = off + 2 * (int)threadIdx.x; j + 1 < len; j += 2 * (int)blockDim.x) {
            int a = s[j], b = s[j + 1];
            if (a > b) { s[j] = b; s[j + 1] = a; }
        }
        __syncthreads();
    }
    for (int i = threadIdx.x; i < len; i += blockDim.x) g_csr[beg + i] = s[i];
}

// ---------------- aggregation: 4 neighbors in parallel, 8B loads ----------------
__global__ void k_agg(const __nv_bfloat16* __restrict__ hin, __nv_bfloat16* __restrict__ hout,
                      const float* __restrict__ bias, const float* __restrict__ linW) {
    int v = blockIdx.x;
    int t = threadIdx.x;
    int g = t >> 6;
    int cg = t & 63;
    int beg = g_rowstart[v], end = g_rowstart[v + 1];
    float dv = g_dinv[v];
    __shared__ int   ssrc[256];
    __shared__ float snorm[256];
    __shared__ float4 red4[3][64];
    __shared__ float reda[64], redb[64];

    float4 acc = make_float4(0.f, 0.f, 0.f, 0.f);
    for (int base = beg; base < end; base += 256) {
        int n = min(256, end - base);
        if (t < n) {
            int s = g_csr[base + t];
            ssrc[t]  = s * HID;
            snorm[t] = g_dinv[s] * dv;
        }
        __syncthreads();
        for (int j = g; j < n; j += 4) {
            uint2 raw = *(const uint2*)(hin + ssrc[j] + cg * 4);
            float wgt = snorm[j];
            __nv_bfloat162 p0 = *(__nv_bfloat162*)&raw.x;
            __nv_bfloat162 p1 = *(__nv_bfloat162*)&raw.y;
            float2 f0 = __bfloat1622float2(p0);
            float2 f1 = __bfloat1622float2(p1);
            acc.x += f0.x * wgt;
            acc.y += f0.y * wgt;
            acc.z += f1.x * wgt;
            acc.w += f1.y * wgt;
        }
        __syncthreads();
    }
    if (g > 0) red4[g - 1][cg] = acc;
    __syncthreads();
    if (t < 64) {
        float4 a = red4[0][t], b = red4[1][t], c = red4[2][t];
        float r0 = acc.x + a.x + b.x + c.x + bias[t * 4 + 0];
        float r1 = acc.y + a.y + b.y + c.y + bias[t * 4 + 1];
        float r2 = acc.z + a.z + b.z + c.z + bias[t * 4 + 2];
        float r3 = acc.w + a.w + b.w + c.w + bias[t * 4 + 3];
        r0 = r0 > 0.f ? r0 : 0.f;
        r1 = r1 > 0.f ? r1 : 0.f;
        r2 = r2 > 0.f ? r2 : 0.f;
        r3 = r3 > 0.f ? r3 : 0.f;
        if (hout) {
            __nv_bfloat16 o[4] = {__float2bfloat16(r0), __float2bfloat16(r1),
                                  __float2bfloat16(r2), __float2bfloat16(r3)};
            *(uint2*)(hout + (size_t)v * HID + t * 4) = *(uint2*)o;
        }
        if (linW) {
            reda[t] = r0 * linW[t*4] + r1 * linW[t*4+1] + r2 * linW[t*4+2] + r3 * linW[t*4+3];
            redb[t] = r0 * linW[HID + t*4]     + r1 * linW[HID + t*4+1]
                    + r2 * linW[HID + t*4+2]   + r3 * linW[HID + t*4+3];
        }
    }
    if (linW) {
        __syncthreads();
        if (t < 32) {
            float a = reda[t] + reda[t + 32];
            float b = redb[t] + redb[t + 32];
#pragma unroll
            for (int off = 16; off > 0; off >>= 1) {
                a += __shfl_down_sync(0xffffffffu, a, off);
                b += __shfl_down_sync(0xffffffffu, b, off);
            }
            if (t == 0) { g_sa[v] = a; g_sb[v] = b; }
        }
    }
}

// ---------------- edge scoring ----------------
__global__ void k_edge_out(const int* __restrict__ src, const int* __restrict__ dst,
                           const float* __restrict__ linb, float* __restrict__ out, int E) {
    int i = blockIdx.x * blockDim.x + threadIdx.x;
    if (i < E) out[i] = g_sa[src[i]] + g_sb[dst[i]] + linb[0];
}

// ---------------- launch ----------------
extern "C" void kernel_launch(void* const* d_in, const int* in_sizes, int n_in,
                              void* d_out, int out_size) {
    const float* x    = (const float*)d_in[0];
    const int*   ei   = (const int*)d_in[1];
    const float* W1   = (const float*)d_in[2];
    const float* b1   = (const float*)d_in[3];
    const float* W2   = (const float*)d_in[4];
    const float* b2   = (const float*)d_in[5];
    const float* linW = (const float*)d_in[6];
    const float* linb = (const float*)d_in[7];
    float* out = (float*)d_out;

    int E = in_sizes[1] / 2;
    const int* esrc = ei;
    const int* edst = ei + E;

    __nv_bfloat16 *hb1, *hb2, *B1, *B2;
    cudaGetSymbolAddress((void**)&hb1, g_hb1);
    cudaGetSymbolAddress((void**)&hb2, g_hb2);
    cudaGetSymbolAddress((void**)&B1, g_B1);
    cudaGetSymbolAddress((void**)&B2, g_B2);

    // one-time setup on the (uncaptured) correctness call
    static cudaStream_t s2 = nullptr;
    static cudaEvent_t ev_fork = nullptr, ev_join = nullptr;
    if (!s2) {
        cudaStreamCreateWithFlags(&s2, cudaStreamNonBlocking);
        cudaEventCreateWithFlags(&ev_fork, cudaEventDisableTiming);
        cudaEventCreateWithFlags(&ev_join, cudaEventDisableTiming);
        cudaFuncSetAttribute(k_hgemm, cudaFuncAttributeMaxDynamicSharedMemorySize, HG_SMEM);
        cudaFuncSetAttribute(k_hgemm_b, cudaFuncAttributeMaxDynamicSharedMemorySize, HG_SMEM);
    }

    // fork: CSR build + prep_B2 run on s2, concurrent with GEMM1 on main stream
    cudaEventRecord(ev_fork, 0);
    cudaStreamWaitEvent(s2, ev_fork, 0);

    k_prep_B<<<dim3(NN / 32, HID / 32), 256>>>(W1, B1, NN);              // 0 (main)
    k_prep_B<<<dim3(HID / 32, HID / 32), 256, 0, s2>>>(W2, B2, HID);     // 1 (s2)
    k_init_deg<<<NN / 256, 256, 0, s2>>>();                              // 2 (s2)
    k_hgemm<<<dim3(NN / 128, 2), 256, HG_SMEM>>>(x, B1, hb1, NN);        // 3 (main) <- ncu

    k_count_deg<<<(E + 255) / 256, 256, 0, s2>>>(edst, E);
    k_scan<<<1, 1024, 0, s2>>>();
    k_fill<<<(E + NN + 255) / 256, 256, 0, s2>>>(esrc, edst, E);
    k_sort_rows<<<NN, 256, 0, s2>>>();

    // join: main stream waits for CSR before aggregation
    cudaEventRecord(ev_join, s2);
    cudaStreamWaitEvent(0, ev_join, 0);

    // layer 1 aggregation: hb1 -> hb2 (bf16)
    k_agg<<<NN, 256>>>(hb1, hb2, b1, (const float*)nullptr);
    // layer 2: GEMM (bf16 A) then agg fused with scores
    k_hgemm_b<<<dim3(NN / 128, 2), 256, HG_SMEM>>>(hb2, B2, hb1, HID);
    k_agg<<<NN, 256>>>(hb1, (__nv_bfloat16*)nullptr, b2, linW);

    // edge scores
    k_edge_out<<<(E + 255) / 256, 256>>>(esrc, edst, linb, out, E);
}

// round 16
// speedup vs baseline: 1.4430x; 1.0485x over previous
#include <cuda_runtime.h>
#include <cuda_bf16.h>
#include <cstdint>

#define NN   16384
#define HID  256
#define NEMAX 1048576
#define ETOT (NEMAX + NN)

// ---------------- device scratch ----------------
__device__ __nv_bfloat16 g_hb1[(size_t)NN * HID];
__device__ __nv_bfloat16 g_hb2[(size_t)NN * HID];
__device__ int   g_deg[NN];
__device__ float g_dinv[NN];
__device__ int   g_rowstart[NN + 1];
__device__ int   g_cursor[NN];
__device__ int   g_csr[ETOT];
__device__ float g_sa[NN];
__device__ float g_sb[NN];
__device__ __nv_bfloat16 g_B1[(size_t)HID * NN];
__device__ __nv_bfloat16 g_B2[(size_t)HID * HID];

__device__ __forceinline__ uint32_t smem_u32(const void* p) {
    uint32_t a;
    asm("{ .reg .u64 t; cvta.to.shared.u64 t, %1; cvt.u32.u64 %0, t; }" : "=r"(a) : "l"(p));
    return a;
}
__device__ __forceinline__ void ldm_x4(uint32_t addr, uint32_t* r) {
    asm volatile("ldmatrix.sync.aligned.m8n8.x4.shared.b16 {%0,%1,%2,%3}, [%4];"
                 : "=r"(r[0]), "=r"(r[1]), "=r"(r[2]), "=r"(r[3]) : "r"(addr));
}
__device__ __forceinline__ void mma_bf16(float* c, const uint32_t* a, const uint32_t* b) {
    asm volatile("mma.sync.aligned.m16n8k16.row.col.f32.bf16.bf16.f32 "
                 "{%0,%1,%2,%3}, {%4,%5,%6,%7}, {%8,%9}, {%0,%1,%2,%3};"
                 : "+f"(c[0]), "+f"(c[1]), "+f"(c[2]), "+f"(c[3])
                 : "r"(a[0]), "r"(a[1]), "r"(a[2]), "r"(a[3]), "r"(b[0]), "r"(b[1]));
}
__device__ __forceinline__ void cp16(uint32_t dst, const void* src) {
    asm volatile("cp.async.cg.shared.global [%0], [%1], 16;" :: "r"(dst), "l"(src));
}
#define CP_COMMIT() asm volatile("cp.async.commit_group;" ::: "memory")
#define CP_WAIT0()  asm volatile("cp.async.wait_group 0;" ::: "memory")
#define CP_WAIT1()  asm volatile("cp.async.wait_group 1;" ::: "memory")

// ---------------- weight prep ----------------
__global__ void k_prep_B(const float* __restrict__ W, __nv_bfloat16* __restrict__ gB, int K) {
    __shared__ float tile[32][33];
    int t = threadIdx.x;
    int k0 = blockIdx.x * 32, n0 = blockIdx.y * 32;
#pragma unroll
    for (int p = 0; p < 4; p++) {
        int idx = t + 256 * p, i = idx >> 5, j = idx & 31;
        tile[i][j] = W[(size_t)(k0 + i) * HID + n0 + j];
    }
    __syncthreads();
    int jp = t >> 3, i0 = (t & 7) * 4;
    __nv_bfloat16 o[4];
#pragma unroll
    for (int q = 0; q < 4; q++) o[q] = __float2bfloat16(tile[i0 + q][jp]);
    *(uint2*)&gB[(size_t)(n0 + jp) * K + k0 + i0] = *(uint2*)o;
}

// ---------------- GEMM epilogue helper ----------------
__device__ __forceinline__ void store_acc_bf16(__nv_bfloat16* C, int HIDc,
                                               float acc[2][8][4], int mo, int wm, int wn,
                                               int lane, int nb) {
#pragma unroll
    for (int mt = 0; mt < 2; mt++) {
        int r0 = mo + wm * 32 + mt * 16 + (lane >> 2);
#pragma unroll
        for (int nt = 0; nt < 8; nt++) {
            int cb = nb + wn * 64 + nt * 8 + (lane & 3) * 2;
            __nv_bfloat162 v0, v1;
            v0.x = __float2bfloat16(acc[mt][nt][0]); v0.y = __float2bfloat16(acc[mt][nt][1]);
            v1.x = __float2bfloat16(acc[mt][nt][2]); v1.y = __float2bfloat16(acc[mt][nt][3]);
            *(__nv_bfloat162*)(C + (size_t)r0 * HIDc + cb)       = v0;
            *(__nv_bfloat162*)(C + (size_t)(r0 + 8) * HIDc + cb) = v1;
        }
    }
}

// ---------------- GEMM (fp32 A): CTA 128x128, BK=32, 3-stage B pipeline, 2 CTA/SM ----
#define TILE_BYTES 10240
#define STAGE_BYTES 20480
#define HG_SMEM (3 * STAGE_BYTES)

__global__ __launch_bounds__(256, 2)
void k_hgemm(const float* __restrict__ A, const __nv_bfloat16* __restrict__ gB,
             __nv_bfloat16* __restrict__ C, int K) {
    extern __shared__ char smem[];
    const uint32_t sb = smem_u32(smem);
    const int t = threadIdx.x;
    const int lane = t & 31, w = t >> 5;
    const int wm = w & 3, wn = w >> 2;
    const int mo = blockIdx.x * 128;
    const int nb = blockIdx.y * 128;
    const int nc = K / 32;

    const int arow = t >> 1, acol = (t & 1) * 16;
    const int brow = t >> 1, bpart = t & 1;
    float4 xa[4];

    auto ldgA = [&](int c) {
        const float* Ap = A + (size_t)(mo + arow) * K + c * 32 + acol;
        xa[0] = *(const float4*)(Ap + 0);
        xa[1] = *(const float4*)(Ap + 4);
        xa[2] = *(const float4*)(Ap + 8);
        xa[3] = *(const float4*)(Ap + 12);
    };
    auto cpB = [&](int c, int st) {
        uint32_t dst = sb + st * STAGE_BYTES + TILE_BYTES + brow * 80 + bpart * 32;
        const __nv_bfloat16* Bp = gB + (size_t)(nb + brow) * K + c * 32 + bpart * 16;
        cp16(dst, Bp);
        cp16(dst + 16, Bp + 8);
    };
    auto stsA = [&](int st) {
        char* base = smem + st * STAGE_BYTES;
        __nv_bfloat16 h[16];
#pragma unroll
        for (int q = 0; q < 4; q++) {
            h[q * 4 + 0] = __float2bfloat16(xa[q].x);
            h[q * 4 + 1] = __float2bfloat16(xa[q].y);
            h[q * 4 + 2] = __float2bfloat16(xa[q].z);
            h[q * 4 + 3] = __float2bfloat16(xa[q].w);
        }
        uint32_t aoff = arow * 80 + acol * 2;
        *(uint4*)(base + aoff)      = *(uint4*)&h[0];
        *(uint4*)(base + aoff + 16) = *(uint4*)&h[8];
    };

    float acc[2][8][4];
#pragma unroll
    for (int i = 0; i < 2; i++)
#pragma unroll
        for (int j = 0; j < 8; j++)
#pragma unroll
            for (int e = 0; e < 4; e++) acc[i][j][e] = 0.f;

    const int lm = lane & 7, sel = lane >> 3;
    const uint32_t a_row_off = (uint32_t)(wm * 32 + (sel & 1) * 8 + lm) * 80 + (uint32_t)(sel >> 1) * 16;
    const uint32_t b_row_off = (uint32_t)(wn * 64 + (sel >> 1) * 8 + lm) * 80 + (uint32_t)(sel & 1) * 16;

    // prologue: B stages 0 and 1 in flight; A stage 0 via registers
    cpB(0, 0); CP_COMMIT();
    if (nc > 1) { cpB(1, 1); CP_COMMIT(); }
    ldgA(0);
    stsA(0);
    if (nc > 1) { CP_WAIT1(); } else { CP_WAIT0(); }
    __syncthreads();

    for (int c = 0; c < nc; c++) {
        const int st = c % 3;
        if (c + 2 < nc) { cpB(c + 2, (c + 2) % 3); CP_COMMIT(); }
        if (c + 1 < nc) ldgA(c + 1);

        const uint32_t stage = sb + st * STAGE_BYTES;
#pragma unroll
        for (int kk = 0; kk < 2; kk++) {
            const uint32_t kb = (uint32_t)kk * 32;
            uint32_t a[2][4];
#pragma unroll
            for (int mt = 0; mt < 2; mt++)
                ldm_x4(stage + a_row_off + (uint32_t)mt * (16 * 80) + kb, a[mt]);
            uint32_t b[8][2];
#pragma unroll
            for (int pr = 0; pr < 4; pr++) {
                uint32_t r[4];
                ldm_x4(stage + TILE_BYTES + b_row_off + (uint32_t)pr * (16 * 80) + kb, r);
                b[2 * pr][0] = r[0]; b[2 * pr][1] = r[1];
                b[2 * pr + 1][0] = r[2]; b[2 * pr + 1][1] = r[3];
            }
#pragma unroll
            for (int mt = 0; mt < 2; mt++)
#pragma unroll
                for (int nt = 0; nt < 8; nt++) mma_bf16(acc[mt][nt], a[mt], b[nt]);
        }
        if (c + 1 < nc) stsA((c + 1) % 3);
        // need B(c+1) resident; allow B(c+2) still in flight
        if (c + 2 < nc) { CP_WAIT1(); } else { CP_WAIT0(); }
        __syncthreads();
    }
    store_acc_bf16(C, HID, acc, mo, wm, wn, lane, nb);
}

// ---------------- GEMM (bf16 A via cp.async): 3-stage A+B pipeline ----------------
__global__ __launch_bounds__(256, 2)
void k_hgemm_b(const __nv_bfloat16* __restrict__ A, const __nv_bfloat16* __restrict__ gB,
               __nv_bfloat16* __restrict__ C, int K) {
    extern __shared__ char smem[];
    const uint32_t sb = smem_u32(smem);
    const int t = threadIdx.x;
    const int lane = t & 31, w = t >> 5;
    const int wm = w & 3, wn = w >> 2;
    const int mo = blockIdx.x * 128;
    const int nb = blockIdx.y * 128;
    const int nc = K / 32;

    const int arow = t >> 1, apart = t & 1;
    const int brow = t >> 1, bpart = t & 1;

    auto cpAB = [&](int c, int st) {
        uint32_t adst = sb + st * STAGE_BYTES + arow * 80 + apart * 32;
        const __nv_bfloat16* Ap = A + (size_t)(mo + arow) * K + c * 32 + apart * 16;
        cp16(adst, Ap);
        cp16(adst + 16, Ap + 8);
        uint32_t bdst = sb + st * STAGE_BYTES + TILE_BYTES + brow * 80 + bpart * 32;
        const __nv_bfloat16* Bp = gB + (size_t)(nb + brow) * K + c * 32 + bpart * 16;
        cp16(bdst, Bp);
        cp16(bdst + 16, Bp + 8);
    };

    float acc[2][8][4];
#pragma unroll
    for (int i = 0; i < 2; i++)
#pragma unroll
        for (int j = 0; j < 8; j++)
#pragma unroll
            for (int e = 0; e < 4; e++) acc[i][j][e] = 0.f;

    const int lm = lane & 7, sel = lane >> 3;
    const uint32_t a_row_off = (uint32_t)(wm * 32 + (sel & 1) * 8 + lm) * 80 + (uint32_t)(sel >> 1) * 16;
    const uint32_t b_row_off = (uint32_t)(wn * 64 + (sel >> 1) * 8 + lm) * 80 + (uint32_t)(sel & 1) * 16;

    cpAB(0, 0); CP_COMMIT();
    if (nc > 1) { cpAB(1, 1); CP_COMMIT(); }
    if (nc > 1) { CP_WAIT1(); } else { CP_WAIT0(); }
    __syncthreads();

    for (int c = 0; c < nc; c++) {
        const int st = c % 3;
        if (c + 2 < nc) { cpAB(c + 2, (c + 2) % 3); CP_COMMIT(); }

        const uint32_t stage = sb + st * STAGE_BYTES;
#pragma unroll
        for (int kk = 0; kk < 2; kk++) {
            const uint32_t kb = (uint32_t)kk * 32;
            uint32_t a[2][4];
#pragma unroll
            for (int mt = 0; mt < 2; mt++)
                ldm_x4(stage + a_row_off + (uint32_t)mt * (16 * 80) + kb, a[mt]);
            uint32_t b[8][2];
#pragma unroll
            for (int pr = 0; pr < 4; pr++) {
                uint32_t r[4];
                ldm_x4(stage + TILE_BYTES + b_row_off + (uint32_t)pr * (16 * 80) + kb, r);
                b[2 * pr][0] = r[0]; b[2 * pr][1] = r[1];
                b[2 * pr + 1][0] = r[2]; b[2 * pr + 1][1] = r[3];
            }
#pragma unroll
            for (int mt = 0; mt < 2; mt++)
#pragma unroll
                for (int nt = 0; nt < 8; nt++) mma_bf16(acc[mt][nt], a[mt], b[nt]);
        }
        if (c + 2 < nc) { CP_WAIT1(); } else { CP_WAIT0(); }
        __syncthreads();
    }
    store_acc_bf16(C, HID, acc, mo, wm, wn, lane, nb);
}

// ---------------- degree / CSR construction ----------------
__global__ void k_init_deg() {
    int i = blockIdx.x * blockDim.x + threadIdx.x;
    if (i < NN) g_deg[i] = 1;
}
__global__ void k_count_deg(const int* __restrict__ dst, int E) {
    int i = blockIdx.x * blockDim.x + threadIdx.x;
    if (i < E) atomicAdd(&g_deg[dst[i]], 1);
}
__global__ void k_scan() {
    __shared__ int sh[1024];
    int tid = threadIdx.x;
    int local[16];
    int sum = 0;
#pragma unroll
    for (int i = 0; i < 16; i++) {
        int d = g_deg[tid * 16 + i];
        local[i] = d;
        g_dinv[tid * 16 + i] = rsqrtf((float)d);
        sum += d;
    }
    sh[tid] = sum;
    __syncthreads();
    for (int off = 1; off < 1024; off <<= 1) {
        int v = (tid >= off) ? sh[tid - off] : 0;
        __syncthreads();
        sh[tid] += v;
        __syncthreads();
    }
    int run = (tid == 0) ? 0 : sh[tid - 1];
#pragma unroll
    for (int i = 0; i < 16; i++) {
        g_rowstart[tid * 16 + i] = run;
        g_cursor[tid * 16 + i]   = run;
        run += local[i];
    }
    if (tid == 1023) g_rowstart[NN] = run;
}
__global__ void k_fill(const int* __restrict__ src, const int* __restrict__ dst, int E) {
    int i = blockIdx.x * blockDim.x + threadIdx.x;
    if (i >= E + NN) return;
    int s, d;
    if (i < E) { s = src[i]; d = dst[i]; }
    else       { s = i - E; d = s; }
    int slot = atomicAdd(&g_cursor[d], 1);
    g_csr[slot] = s;
}
__global__ void k_sort_rows() {
    __shared__ int s[1024];
    int r = blockIdx.x;
    int beg = g_rowstart[r], end = g_rowstart[r + 1];
    int len = end - beg;
    if (len <= 1 || len > 1024) return;
    for (int i = threadIdx.x; i < len; i += blockDim.x) s[i] = g_csr[beg + i];
    __syncthreads();
    for (int ph = 0; ph < len; ph++) {
        int off = ph & 1;
        for (int j = off + 2 * (int)threadIdx.x; j + 1 < len; j += 2 * (int)blockDim.x) {
            int a = s[j], b = s[j + 1];
            if (a > b) { s[j] = b; s[j + 1] = a; }
        }
        __syncthreads();
    }
    for (int i = threadIdx.x; i < len; i += blockDim.x) g_csr[beg + i] = s[i];
}

// ---------------- aggregation: 4 neighbors in parallel, 8B loads ----------------
__global__ void k_agg(const __nv_bfloat16* __restrict__ hin, __nv_bfloat16* __restrict__ hout,
                      const float* __restrict__ bias, const float* __restrict__ linW) {
    int v = blockIdx.x;
    int t = threadIdx.x;
    int g = t >> 6;
    int cg = t & 63;
    int beg = g_rowstart[v], end = g_rowstart[v + 1];
    float dv = g_dinv[v];
    __shared__ int   ssrc[256];
    __shared__ float snorm[256];
    __shared__ float4 red4[3][64];
    __shared__ float reda[64], redb[64];

    float4 acc = make_float4(0.f, 0.f, 0.f, 0.f);
    for (int base = beg; base < end; base += 256) {
        int n = min(256, end - base);
        if (t < n) {
            int s = g_csr[base + t];
            ssrc[t]  = s * HID;
            snorm[t] = g_dinv[s] * dv;
        }
        __syncthreads();
        for (int j = g; j < n; j += 4) {
            uint2 raw = *(const uint2*)(hin + ssrc[j] + cg * 4);
            float wgt = snorm[j];
            __nv_bfloat162 p0 = *(__nv_bfloat162*)&raw.x;
            __nv_bfloat162 p1 = *(__nv_bfloat162*)&raw.y;
            float2 f0 = __bfloat1622float2(p0);
            float2 f1 = __bfloat1622float2(p1);
            acc.x += f0.x * wgt;
            acc.y += f0.y * wgt;
            acc.z += f1.x * wgt;
            acc.w += f1.y * wgt;
        }
        __syncthreads();
    }
    if (g > 0) red4[g - 1][cg] = acc;
    __syncthreads();
    if (t < 64) {
        float4 a = red4[0][t], b = red4[1][t], c = red4[2][t];
        float r0 = acc.x + a.x + b.x + c.x + bias[t * 4 + 0];
        float r1 = acc.y + a.y + b.y + c.y + bias[t * 4 + 1];
        float r2 = acc.z + a.z + b.z + c.z + bias[t * 4 + 2];
        float r3 = acc.w + a.w + b.w + c.w + bias[t * 4 + 3];
        r0 = r0 > 0.f ? r0 : 0.f;
        r1 = r1 > 0.f ? r1 : 0.f;
        r2 = r2 > 0.f ? r2 : 0.f;
        r3 = r3 > 0.f ? r3 : 0.f;
        if (hout) {
            __nv_bfloat16 o[4] = {__float2bfloat16(r0), __float2bfloat16(r1),
                                  __float2bfloat16(r2), __float2bfloat16(r3)};
            *(uint2*)(hout + (size_t)v * HID + t * 4) = *(uint2*)o;
        }
        if (linW) {
            reda[t] = r0 * linW[t*4] + r1 * linW[t*4+1] + r2 * linW[t*4+2] + r3 * linW[t*4+3];
            redb[t] = r0 * linW[HID + t*4]     + r1 * linW[HID + t*4+1]
                    + r2 * linW[HID + t*4+2]   + r3 * linW[HID + t*4+3];
        }
    }
    if (linW) {
        __syncthreads();
        if (t < 32) {
            float a = reda[t] + reda[t + 32];
            float b = redb[t] + redb[t + 32];
#pragma unroll
            for (int off = 16; off > 0; off >>= 1) {
                a += __shfl_down_sync(0xffffffffu, a, off);
                b += __shfl_down_sync(0xffffffffu, b, off);
            }
            if (t == 0) { g_sa[v] = a; g_sb[v] = b; }
        }
    }
}

// ---------------- edge scoring ----------------
__global__ void k_edge_out(const int* __restrict__ src, const int* __restrict__ dst,
                           const float* __restrict__ linb, float* __restrict__ out, int E) {
    int i = blockIdx.x * blockDim.x + threadIdx.x;
    if (i < E) out[i] = g_sa[src[i]] + g_sb[dst[i]] + linb[0];
}

// ---------------- launch ----------------
extern "C" void kernel_launch(void* const* d_in, const int* in_sizes, int n_in,
                              void* d_out, int out_size) {
    const float* x    = (const float*)d_in[0];
    const int*   ei   = (const int*)d_in[1];
    const float* W1   = (const float*)d_in[2];
    const float* b1   = (const float*)d_in[3];
    const float* W2   = (const float*)d_in[4];
    const float* b2   = (const float*)d_in[5];
    const float* linW = (const float*)d_in[6];
    const float* linb = (const float*)d_in[7];
    float* out = (float*)d_out;

    int E = in_sizes[1] / 2;
    const int* esrc = ei;
    const int* edst = ei + E;

    __nv_bfloat16 *hb1, *hb2, *B1, *B2;
    cudaGetSymbolAddress((void**)&hb1, g_hb1);
    cudaGetSymbolAddress((void**)&hb2, g_hb2);
    cudaGetSymbolAddress((void**)&B1, g_B1);
    cudaGetSymbolAddress((void**)&B2, g_B2);

    // one-time setup on the (uncaptured) correctness call
    static cudaStream_t s2 = nullptr;
    static cudaEvent_t ev_fork = nullptr, ev_join = nullptr;
    if (!s2) {
        cudaStreamCreateWithFlags(&s2, cudaStreamNonBlocking);
        cudaEventCreateWithFlags(&ev_fork, cudaEventDisableTiming);
        cudaEventCreateWithFlags(&ev_join, cudaEventDisableTiming);
        cudaFuncSetAttribute(k_hgemm, cudaFuncAttributeMaxDynamicSharedMemorySize, HG_SMEM);
        cudaFuncSetAttribute(k_hgemm_b, cudaFuncAttributeMaxDynamicSharedMemorySize, HG_SMEM);
    }

    // fork: CSR build + prep_B2 run on s2, concurrent with GEMM1 on main stream
    cudaEventRecord(ev_fork, 0);
    cudaStreamWaitEvent(s2, ev_fork, 0);

    k_prep_B<<<dim3(NN / 32, HID / 32), 256>>>(W1, B1, NN);              // 0 (main)
    k_prep_B<<<dim3(HID / 32, HID / 32), 256, 0, s2>>>(W2, B2, HID);     // 1 (s2)
    k_init_deg<<<NN / 256, 256, 0, s2>>>();                              // 2 (s2)
    k_hgemm<<<dim3(NN / 128, 2), 256, HG_SMEM>>>(x, B1, hb1, NN);        // 3 (main) <- ncu

    k_count_deg<<<(E + 255) / 256, 256, 0, s2>>>(edst, E);
    k_scan<<<1, 1024, 0, s2>>>();
    k_fill<<<(E + NN + 255) / 256, 256, 0, s2>>>(esrc, edst, E);
    k_sort_rows<<<NN, 256, 0, s2>>>();

    // join: main stream waits for CSR before aggregation
    cudaEventRecord(ev_join, s2);
    cudaStreamWaitEvent(0, ev_join, 0);

    // layer 1 aggregation: hb1 -> hb2 (bf16)
    k_agg<<<NN, 256>>>(hb1, hb2, b1, (const float*)nullptr);
    // layer 2: GEMM (bf16 A) then agg fused with scores
    k_hgemm_b<<<dim3(NN / 128, 2), 256, HG_SMEM>>>(hb2, B2, hb1, HID);
    k_agg<<<NN, 256>>>(hb1, (__nv_bfloat16*)nullptr, b2, linW);

    // edge scores
    k_edge_out<<<(E + 255) / 256, 256>>>(esrc, edst, linb, out, E);
}